// round 11
// baseline (speedup 1.0000x reference)
#include <cuda_runtime.h>
#include <math.h>
#include <stdint.h>

#define S_LEN    2048
#define DIM      3072
#define HEADS    24
#define HEAD_DIM 128

// Scratch (no cudaMalloc allowed): q, k, v post-projection
__device__ float g_q[S_LEN * DIM];
__device__ float g_k[S_LEN * DIM];
__device__ float g_v[S_LEN * DIM];

// ---- helpers -------------------------------------------------------------
__device__ __forceinline__ uint32_t tf32_rna(float x) {
    uint32_t r;
    asm("cvt.rna.tf32.f32 %0, %1;" : "=r"(r) : "f"(x));
    return r;
}
__device__ __forceinline__ void mma_tf32(float c[4], const uint32_t a[4], const uint32_t b[2]) {
    asm volatile(
        "mma.sync.aligned.m16n8k8.row.col.f32.tf32.tf32.f32 "
        "{%0,%1,%2,%3}, {%4,%5,%6,%7}, {%8,%9}, {%0,%1,%2,%3};"
        : "+f"(c[0]), "+f"(c[1]), "+f"(c[2]), "+f"(c[3])
        : "r"(a[0]), "r"(a[1]), "r"(a[2]), "r"(a[3]), "r"(b[0]), "r"(b[1]));
}
__device__ __forceinline__ void cp_async16(uint32_t smem_dst, const void* gsrc) {
    asm volatile("cp.async.cg.shared.global [%0], [%1], 16;"
                 :: "r"(smem_dst), "l"(gsrc));
}
__device__ __forceinline__ void cp_commit() {
    asm volatile("cp.async.commit_group;" ::: "memory");
}
template <int N>
__device__ __forceinline__ void cp_wait() {
    asm volatile("cp.async.wait_group %0;" :: "n"(N) : "memory");
}

// ===========================================================================
// Stage 1: QKV projection via mma.sync tf32.
// CTA tile 128x128, 4 warps (2m x 2n), warp tile 64x64 (4i x 8j of m16n8k8)
// -> same 125 B LDS per MMA as round 9/10, but 2 CTAs/SM so each SMSP holds
// warps from two independent CTAs (sync stalls overlap with compute).
// K-chunk 32, 3-stage cp.async pipeline, one __syncthreads per chunk.
// Strides: A 36 (banks 4g+tg bijective), B 136 (banks 8tg+g bijective).
// ===========================================================================
#define QTHREADS 128
#define QA_STRIDE 36
#define QB_STRIDE 136
#define QA_FLOATS (128 * QA_STRIDE)              // 4608
#define QB_FLOATS (32 * QB_STRIDE)               // 4352
#define QBUF_FLOATS (QA_FLOATS + QB_FLOATS)      // 8960
#define QSTAGES 3
#define QSMEM_BYTES (QSTAGES * QBUF_FLOATS * 4)  // 107520 -> 2 CTAs/SM
#define NCHUNK (DIM / 32)                        // 96

__global__ __launch_bounds__(QTHREADS, 2) void qkv_mma_kernel(
    const float* __restrict__ x,
    const float* __restrict__ Wq, const float* __restrict__ bq,
    const float* __restrict__ Wk, const float* __restrict__ bk,
    const float* __restrict__ Wv, const float* __restrict__ bv)
{
    extern __shared__ float smem[];
    const float* W; const float* bias; float* out;
    if (blockIdx.z == 0)      { W = Wq; bias = bq; out = g_q; }
    else if (blockIdx.z == 1) { W = Wk; bias = bk; out = g_k; }
    else                      { W = Wv; bias = bv; out = g_v; }

    const int tid  = threadIdx.x;
    const int wid  = tid >> 5;
    const int lane = tid & 31;
    const int g    = lane >> 2;
    const int tg   = lane & 3;
    const int wm   = wid >> 1;       // 0..1 -> rows 64*wm
    const int wn   = wid & 1;        // 0..1 -> cols 64*wn
    const int row0 = blockIdx.y * 128;
    const int col0 = blockIdx.x * 128;

    // fill indices: A 128x32 floats (1 row/thread, 8 x 16B), B 32x128 (8 x 16B)
    const int brow = tid >> 2;              // 0..31
    const int bcol = (tid & 3) * 32;        // 0/32/64/96

    const float* xA = x + (size_t)(row0 + tid) * DIM;          // + c*32
    const float* wB = W + (size_t)brow * DIM + col0 + bcol;    // + c*32*DIM

    const uint32_t smem_u32 = (uint32_t)__cvta_generic_to_shared(smem);
    auto As = [&](int b) -> uint32_t { return smem_u32 + (uint32_t)(b * QBUF_FLOATS) * 4u; };
    auto Bs = [&](int b) -> uint32_t { return As(b) + QA_FLOATS * 4u; };

    auto issue_chunk = [&](int c, int b) {
        const float* asrc = xA + c * 32;
        const uint32_t adst = As(b) + (uint32_t)(tid * QA_STRIDE) * 4u;
        #pragma unroll
        for (int j = 0; j < 8; j++)
            cp_async16(adst + j * 16u, asrc + j * 4);
        const float* bsrc = wB + (size_t)(c * 32) * DIM;
        const uint32_t bdst = Bs(b) + (uint32_t)(brow * QB_STRIDE + bcol) * 4u;
        #pragma unroll
        for (int j = 0; j < 8; j++)
            cp_async16(bdst + j * 16u, bsrc + j * 4);
    };

    float acc[4][8][4];
    #pragma unroll
    for (int i = 0; i < 4; i++)
        #pragma unroll
        for (int j = 0; j < 8; j++)
            #pragma unroll
            for (int r = 0; r < 4; r++) acc[i][j][r] = 0.f;

    issue_chunk(0, 0); cp_commit();
    issue_chunk(1, 1); cp_commit();

    for (int c = 0; c < NCHUNK; c++) {
        const int b = c % QSTAGES;
        cp_wait<1>();          // groups pending: {c, c+1} -> chunk c complete
        __syncthreads();       // also: all warps finished reading buffer of c-1
        if (c + 2 < NCHUNK) issue_chunk(c + 2, (c + 2) % QSTAGES);
        cp_commit();           // always commit (possibly empty) to keep counts exact

        const float* Ap = smem + (size_t)b * QBUF_FLOATS;
        const float* Bp = smem + (size_t)b * QBUF_FLOATS + QA_FLOATS;

        #pragma unroll
        for (int kk8 = 0; kk8 < 4; kk8++) {
            const int kk = kk8 * 8;
            uint32_t bb[8][2];
            #pragma unroll
            for (int j = 0; j < 8; j++) {
                const int n = wn * 64 + j * 8 + g;
                bb[j][0] = tf32_rna(Bp[(kk + tg)     * QB_STRIDE + n]);
                bb[j][1] = tf32_rna(Bp[(kk + tg + 4) * QB_STRIDE + n]);
            }
            #pragma unroll
            for (int i = 0; i < 4; i++) {
                const int r = wm * 64 + i * 16 + g;
                uint32_t ah[4];
                ah[0] = tf32_rna(Ap[(r)     * QA_STRIDE + kk + tg]);
                ah[1] = tf32_rna(Ap[(r + 8) * QA_STRIDE + kk + tg]);
                ah[2] = tf32_rna(Ap[(r)     * QA_STRIDE + kk + tg + 4]);
                ah[3] = tf32_rna(Ap[(r + 8) * QA_STRIDE + kk + tg + 4]);
                #pragma unroll
                for (int j = 0; j < 8; j++)
                    mma_tf32(acc[i][j], ah, bb[j]);
            }
        }
    }

    // ---- epilogue: add bias, store ----
    #pragma unroll
    for (int j = 0; j < 8; j++) {
        const int n = col0 + wn * 64 + j * 8 + 2 * tg;
        const float2 bb = *(const float2*)(bias + n);
        #pragma unroll
        for (int i = 0; i < 4; i++) {
            const int r = row0 + wm * 64 + i * 16 + g;
            float2 o0 = make_float2(acc[i][j][0] + bb.x, acc[i][j][1] + bb.y);
            float2 o1 = make_float2(acc[i][j][2] + bb.x, acc[i][j][3] + bb.y);
            *(float2*)(out + (size_t)r * DIM + n)       = o0;
            *(float2*)(out + (size_t)(r + 8) * DIM + n) = o1;
        }
    }
}

// ---------------------------------------------------------------------------
// Stage 2: per-head RMSNorm + RoPE applied in place to g_q and g_k.
// ---------------------------------------------------------------------------
__global__ __launch_bounds__(256) void rms_rope_kernel(
    const float* __restrict__ cosb, const float* __restrict__ sinb,
    const float* __restrict__ gq, const float* __restrict__ gk)
{
    const int gw   = (blockIdx.x * blockDim.x + threadIdx.x) >> 5;
    const int lane = threadIdx.x & 31;
    const int rows = S_LEN * HEADS;
    if (gw >= 2 * rows) return;

    const int t  = (gw >= rows) ? 1 : 0;
    const int rr = t ? (gw - rows) : gw;
    const int s  = rr / HEADS;

    float* ptr = (t ? g_k : g_q) + (size_t)rr * HEAD_DIM;
    const float* g = t ? gk : gq;

    float4 vx = *(float4*)(ptr + lane * 4);
    float ss = vx.x * vx.x + vx.y * vx.y + vx.z * vx.z + vx.w * vx.w;
    #pragma unroll
    for (int o = 16; o > 0; o >>= 1) ss += __shfl_xor_sync(0xffffffffu, ss, o);
    const float rnorm = rsqrtf(ss * (1.0f / HEAD_DIM) + 1e-6f);

    float4 gg = *(const float4*)(g + lane * 4);
    vx.x *= rnorm * gg.x; vx.y *= rnorm * gg.y;
    vx.z *= rnorm * gg.z; vx.w *= rnorm * gg.w;

    float4 c  = *(const float4*)(cosb + (size_t)s * HEAD_DIM + lane * 4);
    float4 sn = *(const float4*)(sinb + (size_t)s * HEAD_DIM + lane * 4);
    float4 o;
    o.x = vx.x * c.x - vx.y * sn.x;
    o.y = vx.y * c.y + vx.x * sn.y;
    o.z = vx.z * c.z - vx.w * sn.z;
    o.w = vx.w * c.w + vx.z * sn.w;
    *(float4*)(ptr + lane * 4) = o;
}

// ===========================================================================
// Stage 3: flash attention on mma.sync tf32, single-pass tf32 (round-10,
// validated: ~630us, rel_err contribution ~3.9e-4).
// ===========================================================================
#define AT_THREADS 256
#define AT_QH 0
#define AT_KS (AT_QH + 64*132)
#define AT_VS (AT_KS + 64*132)
#define AT_PH (AT_VS + 64*136)
#define AT_RMAX (AT_PH + 64*68)
#define AT_RSUM (AT_RMAX + 128)
#define AT_TOTAL (AT_RSUM + 128)
#define AT_SMEM_BYTES (AT_TOTAL * 4)

__global__ __launch_bounds__(AT_THREADS, 1) void attn_mma_kernel(float* __restrict__ out)
{
    extern __shared__ uint32_t smu[];
    uint32_t* Qh = smu + AT_QH;
    uint32_t* Ks = smu + AT_KS;
    uint32_t* Vs = smu + AT_VS;
    uint32_t* Ph = smu + AT_PH;
    float* Rmax = (float*)(smu + AT_RMAX);
    float* Rsum = (float*)(smu + AT_RSUM);

    const int h    = blockIdx.y;
    const int q0   = blockIdx.x * 64;
    const int tid  = threadIdx.x;
    const int wid  = tid >> 5;
    const int lane = tid & 31;
    const int g    = lane >> 2;
    const int tg   = lane & 3;
    const int wm   = wid & 3;
    const int wh   = wid >> 2;
    const int ri0  = wm * 16 + g;
    const int ri1  = ri0 + 8;

    const float scale = 0.08838834764831845f;

    for (int i = tid; i < 64 * 32; i += AT_THREADS) {
        const int r  = i >> 5;
        const int c4 = (i & 31) * 4;
        float4 v = *(const float4*)(g_q + ((size_t)(q0 + r) * HEADS + h) * HEAD_DIM + c4);
        uint4 hh;
        hh.x = tf32_rna(v.x * scale);
        hh.y = tf32_rna(v.y * scale);
        hh.z = tf32_rna(v.z * scale);
        hh.w = tf32_rna(v.w * scale);
        *(uint4*)(Qh + r * 132 + c4) = hh;
    }

    float m0 = -INFINITY, m1 = -INFINITY, l0 = 0.f, l1 = 0.f;
    float o[8][4];
    #pragma unroll
    for (int j = 0; j < 8; j++)
        #pragma unroll
        for (int r = 0; r < 4; r++) o[j][r] = 0.f;

    for (int kv0 = 0; kv0 < S_LEN; kv0 += 64) {
        __syncthreads();
        for (int i = tid; i < 64 * 32; i += AT_THREADS) {
            const int r  = i >> 5;
            const int c4 = (i & 31) * 4;
            float4 kv4 = *(const float4*)(g_k + ((size_t)(kv0 + r) * HEADS + h) * HEAD_DIM + c4);
            uint4 t;
            t.x = tf32_rna(kv4.x); t.y = tf32_rna(kv4.y);
            t.z = tf32_rna(kv4.z); t.w = tf32_rna(kv4.w);
            *(uint4*)(Ks + r * 132 + c4) = t;
            float4 vv4 = *(const float4*)(g_v + ((size_t)(kv0 + r) * HEADS + h) * HEAD_DIM + c4);
            uint4 u;
            u.x = tf32_rna(vv4.x); u.y = tf32_rna(vv4.y);
            u.z = tf32_rna(vv4.z); u.w = tf32_rna(vv4.w);
            *(uint4*)(Vs + r * 136 + c4) = u;
        }
        __syncthreads();

        // ---- S = Q K^T ----
        float s[4][4];
        #pragma unroll
        for (int j = 0; j < 4; j++)
            #pragma unroll
            for (int r = 0; r < 4; r++) s[j][r] = 0.f;

        #pragma unroll
        for (int kk8 = 0; kk8 < 16; kk8++) {
            const int kk = kk8 * 8;
            uint32_t ah[4];
            ah[0] = Qh[ri0 * 132 + kk + tg];
            ah[1] = Qh[ri1 * 132 + kk + tg];
            ah[2] = Qh[ri0 * 132 + kk + tg + 4];
            ah[3] = Qh[ri1 * 132 + kk + tg + 4];
            #pragma unroll
            for (int j = 0; j < 4; j++) {
                const int nv = wh * 32 + j * 8 + g;
                uint32_t bb[2];
                bb[0] = Ks[nv * 132 + kk + tg];
                bb[1] = Ks[nv * 132 + kk + tg + 4];
                mma_tf32(s[j], ah, bb);
            }
        }

        // ---- row max ----
        float mx0 = fmaxf(fmaxf(s[0][0], s[0][1]), fmaxf(s[1][0], s[1][1]));
        mx0 = fmaxf(mx0, fmaxf(fmaxf(s[2][0], s[2][1]), fmaxf(s[3][0], s[3][1])));
        float mx1 = fmaxf(fmaxf(s[0][2], s[0][3]), fmaxf(s[1][2], s[1][3]));
        mx1 = fmaxf(mx1, fmaxf(fmaxf(s[2][2], s[2][3]), fmaxf(s[3][2], s[3][3])));
        mx0 = fmaxf(mx0, __shfl_xor_sync(0xffffffffu, mx0, 1));
        mx0 = fmaxf(mx0, __shfl_xor_sync(0xffffffffu, mx0, 2));
        mx1 = fmaxf(mx1, __shfl_xor_sync(0xffffffffu, mx1, 1));
        mx1 = fmaxf(mx1, __shfl_xor_sync(0xffffffffu, mx1, 2));
        if (tg == 0) {
            Rmax[wh * 64 + ri0] = mx0;
            Rmax[wh * 64 + ri1] = mx1;
        }
        __syncthreads();
        const float mn0 = fmaxf(m0, fmaxf(Rmax[ri0], Rmax[64 + ri0]));
        const float mn1 = fmaxf(m1, fmaxf(Rmax[ri1], Rmax[64 + ri1]));
        const float alpha0 = __expf(m0 - mn0);
        const float alpha1 = __expf(m1 - mn1);

        // ---- p = exp(s - m), stage tf32 P, partial row sums ----
        float sum0 = 0.f, sum1 = 0.f;
        #pragma unroll
        for (int j = 0; j < 4; j++) {
            const int col = wh * 32 + j * 8 + 2 * tg;
            const float p0 = __expf(s[j][0] - mn0);
            const float p1 = __expf(s[j][1] - mn0);
            const float p2 = __expf(s[j][2] - mn1);
            const float p3 = __expf(s[j][3] - mn1);
            sum0 += p0 + p1;
            sum1 += p2 + p3;
            Ph[ri0 * 68 + col]     = tf32_rna(p0);
            Ph[ri0 * 68 + col + 1] = tf32_rna(p1);
            Ph[ri1 * 68 + col]     = tf32_rna(p2);
            Ph[ri1 * 68 + col + 1] = tf32_rna(p3);
        }
        sum0 += __shfl_xor_sync(0xffffffffu, sum0, 1);
        sum0 += __shfl_xor_sync(0xffffffffu, sum0, 2);
        sum1 += __shfl_xor_sync(0xffffffffu, sum1, 1);
        sum1 += __shfl_xor_sync(0xffffffffu, sum1, 2);
        if (tg == 0) {
            Rsum[wh * 64 + ri0] = sum0;
            Rsum[wh * 64 + ri1] = sum1;
        }
        __syncthreads();
        l0 = l0 * alpha0 + Rsum[ri0] + Rsum[64 + ri0];
        l1 = l1 * alpha1 + Rsum[ri1] + Rsum[64 + ri1];
        m0 = mn0; m1 = mn1;

        #pragma unroll
        for (int j = 0; j < 8; j++) {
            o[j][0] *= alpha0; o[j][1] *= alpha0;
            o[j][2] *= alpha1; o[j][3] *= alpha1;
        }

        // ---- O += P V ----
        #pragma unroll
        for (int kk8 = 0; kk8 < 8; kk8++) {
            const int kk = kk8 * 8;
            uint32_t ah[4];
            ah[0] = Ph[ri0 * 68 + kk + tg];
            ah[1] = Ph[ri1 * 68 + kk + tg];
            ah[2] = Ph[ri0 * 68 + kk + tg + 4];
            ah[3] = Ph[ri1 * 68 + kk + tg + 4];
            #pragma unroll
            for (int j = 0; j < 8; j++) {
                const int nd = wh * 64 + j * 8 + g;
                uint32_t bb[2];
                bb[0] = Vs[(kk + tg)     * 136 + nd];
                bb[1] = Vs[(kk + tg + 4) * 136 + nd];
                mma_tf32(o[j], ah, bb);
            }
        }
    }

    const float inv0 = 1.f / l0;
    const float inv1 = 1.f / l1;
    #pragma unroll
    for (int j = 0; j < 8; j++) {
        const int d = h * HEAD_DIM + wh * 64 + j * 8 + 2 * tg;
        *(float2*)(out + (size_t)(q0 + ri0) * DIM + d) =
            make_float2(o[j][0] * inv0, o[j][1] * inv0);
        *(float2*)(out + (size_t)(q0 + ri1) * DIM + d) =
            make_float2(o[j][2] * inv1, o[j][3] * inv1);
    }
}

// ---------------------------------------------------------------------------
extern "C" void kernel_launch(void* const* d_in, const int* in_sizes, int n_in,
                              void* d_out, int out_size)
{
    (void)in_sizes; (void)n_in; (void)out_size;
    const float* x  = (const float*)d_in[0];
    const float* cs = (const float*)d_in[1];
    const float* sn = (const float*)d_in[2];
    const float* Wq = (const float*)d_in[3];
    const float* bq = (const float*)d_in[4];
    const float* Wk = (const float*)d_in[5];
    const float* bk = (const float*)d_in[6];
    const float* Wv = (const float*)d_in[7];
    const float* bv = (const float*)d_in[8];
    const float* gq = (const float*)d_in[9];
    const float* gk = (const float*)d_in[10];
    float* out = (float*)d_out;

    // Stage 1: QKV projections (mma.sync tf32, 128x128 CTA, 2 CTAs/SM)
    cudaFuncSetAttribute(qkv_mma_kernel, cudaFuncAttributeMaxDynamicSharedMemorySize,
                         QSMEM_BYTES);
    dim3 gg(DIM / 128, S_LEN / 128, 3);
    qkv_mma_kernel<<<gg, QTHREADS, QSMEM_BYTES>>>(x, Wq, bq, Wk, bk, Wv, bv);

    // Stage 2: RMSNorm + RoPE on q, k
    const int warps  = 2 * S_LEN * HEADS;
    const int thr    = 256;
    const int blocks = (warps * 32 + thr - 1) / thr;
    rms_rope_kernel<<<blocks, thr>>>(cs, sn, gq, gk);

    // Stage 3: attention (mma.sync tf32, single-pass)
    cudaFuncSetAttribute(attn_mma_kernel, cudaFuncAttributeMaxDynamicSharedMemorySize,
                         AT_SMEM_BYTES);
    dim3 ga(S_LEN / 64, HEADS);
    attn_mma_kernel<<<ga, AT_THREADS, AT_SMEM_BYTES>>>(out);
}

// round 12
// speedup vs baseline: 1.1743x; 1.1743x over previous
#include <cuda_runtime.h>
#include <math.h>
#include <stdint.h>

#define S_LEN    2048
#define DIM      3072
#define HEADS    24
#define HEAD_DIM 128

// Scratch (no cudaMalloc allowed): q, k, v post-projection
__device__ float g_q[S_LEN * DIM];
__device__ float g_k[S_LEN * DIM];
__device__ float g_v[S_LEN * DIM];

// ---- helpers -------------------------------------------------------------
__device__ __forceinline__ uint32_t tf32_rna(float x) {
    uint32_t r;
    asm("cvt.rna.tf32.f32 %0, %1;" : "=r"(r) : "f"(x));
    return r;
}
__device__ __forceinline__ void mma_tf32(float c[4], const uint32_t a[4], const uint32_t b[2]) {
    asm volatile(
        "mma.sync.aligned.m16n8k8.row.col.f32.tf32.tf32.f32 "
        "{%0,%1,%2,%3}, {%4,%5,%6,%7}, {%8,%9}, {%0,%1,%2,%3};"
        : "+f"(c[0]), "+f"(c[1]), "+f"(c[2]), "+f"(c[3])
        : "r"(a[0]), "r"(a[1]), "r"(a[2]), "r"(a[3]), "r"(b[0]), "r"(b[1]));
}
__device__ __forceinline__ void cp_async16(uint32_t smem_dst, const void* gsrc) {
    asm volatile("cp.async.cg.shared.global [%0], [%1], 16;"
                 :: "r"(smem_dst), "l"(gsrc));
}
__device__ __forceinline__ void cp_commit() {
    asm volatile("cp.async.commit_group;" ::: "memory");
}
template <int N>
__device__ __forceinline__ void cp_wait() {
    asm volatile("cp.async.wait_group %0;" :: "n"(N) : "memory");
}

// ===========================================================================
// Stage 1: QKV projection via mma.sync tf32.
// CTA tile 128x256, 512 threads, 16 warps (4m x 4n), warp tile 32x64
// (2i x 8j of m16n8k8) -> 4 warps per SMSP inside ONE CTA: warp density up
// without shrinking the tile (round-11 lesson). K-chunk 32, 3-stage cp.async
// pipeline, one __syncthreads per chunk. Raw fp32 in smem, cvt at frag load.
// Strides: A 36 (banks 4g+tg bijective), B 264 (banks 8tg+g bijective).
// ===========================================================================
#define QTHREADS 512
#define QA_STRIDE 36
#define QB_STRIDE 264
#define QA_FLOATS (128 * QA_STRIDE)              // 4608
#define QB_FLOATS (32 * QB_STRIDE)               // 8448
#define QBUF_FLOATS (QA_FLOATS + QB_FLOATS)      // 13056
#define QSTAGES 3
#define QSMEM_BYTES (QSTAGES * QBUF_FLOATS * 4)  // 156672
#define NCHUNK (DIM / 32)                        // 96

__global__ __launch_bounds__(QTHREADS, 1) void qkv_mma_kernel(
    const float* __restrict__ x,
    const float* __restrict__ Wq, const float* __restrict__ bq,
    const float* __restrict__ Wk, const float* __restrict__ bk,
    const float* __restrict__ Wv, const float* __restrict__ bv)
{
    extern __shared__ float smem[];
    const float* W; const float* bias; float* out;
    if (blockIdx.z == 0)      { W = Wq; bias = bq; out = g_q; }
    else if (blockIdx.z == 1) { W = Wk; bias = bk; out = g_k; }
    else                      { W = Wv; bias = bv; out = g_v; }

    const int tid  = threadIdx.x;
    const int wid  = tid >> 5;
    const int lane = tid & 31;
    const int g    = lane >> 2;
    const int tg   = lane & 3;
    const int wm   = wid >> 2;       // 0..3 -> rows 32*wm
    const int wn   = wid & 3;        // 0..3 -> cols 64*wn
    const int row0 = blockIdx.y * 128;
    const int col0 = blockIdx.x * 256;

    // fill indices: A 128x32 floats (2 x 16B/thread), B 32x256 (4 x 16B/thread)
    const int arow = tid >> 2;              // 0..127
    const int acol = (tid & 3) * 8;         // 0/8/16/24
    const int brow = tid >> 4;              // 0..31
    const int bcol = (tid & 15) * 16;       // 0..240

    const float* xA = x + (size_t)(row0 + arow) * DIM + acol;
    const float* wB = W + (size_t)brow * DIM + col0 + bcol;

    const uint32_t smem_u32 = (uint32_t)__cvta_generic_to_shared(smem);
    auto As = [&](int b) -> uint32_t { return smem_u32 + (uint32_t)(b * QBUF_FLOATS) * 4u; };
    auto Bs = [&](int b) -> uint32_t { return As(b) + QA_FLOATS * 4u; };

    auto issue_chunk = [&](int c, int b) {
        const float* asrc = xA + c * 32;
        const uint32_t adst = As(b) + (uint32_t)(arow * QA_STRIDE + acol) * 4u;
        #pragma unroll
        for (int j = 0; j < 2; j++)
            cp_async16(adst + j * 16u, asrc + j * 4);
        const float* bsrc = wB + (size_t)(c * 32) * DIM;
        const uint32_t bdst = Bs(b) + (uint32_t)(brow * QB_STRIDE + bcol) * 4u;
        #pragma unroll
        for (int j = 0; j < 4; j++)
            cp_async16(bdst + j * 16u, bsrc + j * 4);
    };

    float acc[2][8][4];
    #pragma unroll
    for (int i = 0; i < 2; i++)
        #pragma unroll
        for (int j = 0; j < 8; j++)
            #pragma unroll
            for (int r = 0; r < 4; r++) acc[i][j][r] = 0.f;

    issue_chunk(0, 0); cp_commit();
    issue_chunk(1, 1); cp_commit();

    for (int c = 0; c < NCHUNK; c++) {
        const int b = c % QSTAGES;
        cp_wait<1>();          // groups pending: {c, c+1} -> chunk c complete
        __syncthreads();       // also: all warps finished reading buffer of c-1
        if (c + 2 < NCHUNK) issue_chunk(c + 2, (c + 2) % QSTAGES);
        cp_commit();           // always commit (possibly empty) to keep counts exact

        const float* Ap = smem + (size_t)b * QBUF_FLOATS;
        const float* Bp = smem + (size_t)b * QBUF_FLOATS + QA_FLOATS;

        #pragma unroll
        for (int kk8 = 0; kk8 < 4; kk8++) {
            const int kk = kk8 * 8;
            uint32_t bb[8][2];
            #pragma unroll
            for (int j = 0; j < 8; j++) {
                const int n = wn * 64 + j * 8 + g;
                bb[j][0] = tf32_rna(Bp[(kk + tg)     * QB_STRIDE + n]);
                bb[j][1] = tf32_rna(Bp[(kk + tg + 4) * QB_STRIDE + n]);
            }
            #pragma unroll
            for (int i = 0; i < 2; i++) {
                const int r = wm * 32 + i * 16 + g;
                uint32_t ah[4];
                ah[0] = tf32_rna(Ap[(r)     * QA_STRIDE + kk + tg]);
                ah[1] = tf32_rna(Ap[(r + 8) * QA_STRIDE + kk + tg]);
                ah[2] = tf32_rna(Ap[(r)     * QA_STRIDE + kk + tg + 4]);
                ah[3] = tf32_rna(Ap[(r + 8) * QA_STRIDE + kk + tg + 4]);
                #pragma unroll
                for (int j = 0; j < 8; j++)
                    mma_tf32(acc[i][j], ah, bb[j]);
            }
        }
    }

    // ---- epilogue: add bias, store ----
    #pragma unroll
    for (int j = 0; j < 8; j++) {
        const int n = col0 + wn * 64 + j * 8 + 2 * tg;
        const float2 bb = *(const float2*)(bias + n);
        #pragma unroll
        for (int i = 0; i < 2; i++) {
            const int r = row0 + wm * 32 + i * 16 + g;
            float2 o0 = make_float2(acc[i][j][0] + bb.x, acc[i][j][1] + bb.y);
            float2 o1 = make_float2(acc[i][j][2] + bb.x, acc[i][j][3] + bb.y);
            *(float2*)(out + (size_t)r * DIM + n)       = o0;
            *(float2*)(out + (size_t)(r + 8) * DIM + n) = o1;
        }
    }
}

// ---------------------------------------------------------------------------
// Stage 2: per-head RMSNorm + RoPE applied in place to g_q and g_k.
// ---------------------------------------------------------------------------
__global__ __launch_bounds__(256) void rms_rope_kernel(
    const float* __restrict__ cosb, const float* __restrict__ sinb,
    const float* __restrict__ gq, const float* __restrict__ gk)
{
    const int gw   = (blockIdx.x * blockDim.x + threadIdx.x) >> 5;
    const int lane = threadIdx.x & 31;
    const int rows = S_LEN * HEADS;
    if (gw >= 2 * rows) return;

    const int t  = (gw >= rows) ? 1 : 0;
    const int rr = t ? (gw - rows) : gw;
    const int s  = rr / HEADS;

    float* ptr = (t ? g_k : g_q) + (size_t)rr * HEAD_DIM;
    const float* g = t ? gk : gq;

    float4 vx = *(float4*)(ptr + lane * 4);
    float ss = vx.x * vx.x + vx.y * vx.y + vx.z * vx.z + vx.w * vx.w;
    #pragma unroll
    for (int o = 16; o > 0; o >>= 1) ss += __shfl_xor_sync(0xffffffffu, ss, o);
    const float rnorm = rsqrtf(ss * (1.0f / HEAD_DIM) + 1e-6f);

    float4 gg = *(const float4*)(g + lane * 4);
    vx.x *= rnorm * gg.x; vx.y *= rnorm * gg.y;
    vx.z *= rnorm * gg.z; vx.w *= rnorm * gg.w;

    float4 c  = *(const float4*)(cosb + (size_t)s * HEAD_DIM + lane * 4);
    float4 sn = *(const float4*)(sinb + (size_t)s * HEAD_DIM + lane * 4);
    float4 o;
    o.x = vx.x * c.x - vx.y * sn.x;
    o.y = vx.y * c.y + vx.x * sn.y;
    o.z = vx.z * c.z - vx.w * sn.z;
    o.w = vx.w * c.w + vx.z * sn.w;
    *(float4*)(ptr + lane * 4) = o;
}

// ===========================================================================
// Stage 3: flash attention on mma.sync tf32, single-pass tf32 (round-10,
// validated: ~630us, rel_err contribution ~3.9e-4).
// ===========================================================================
#define AT_THREADS 256
#define AT_QH 0
#define AT_KS (AT_QH + 64*132)
#define AT_VS (AT_KS + 64*132)
#define AT_PH (AT_VS + 64*136)
#define AT_RMAX (AT_PH + 64*68)
#define AT_RSUM (AT_RMAX + 128)
#define AT_TOTAL (AT_RSUM + 128)
#define AT_SMEM_BYTES (AT_TOTAL * 4)

__global__ __launch_bounds__(AT_THREADS, 1) void attn_mma_kernel(float* __restrict__ out)
{
    extern __shared__ uint32_t smu[];
    uint32_t* Qh = smu + AT_QH;
    uint32_t* Ks = smu + AT_KS;
    uint32_t* Vs = smu + AT_VS;
    uint32_t* Ph = smu + AT_PH;
    float* Rmax = (float*)(smu + AT_RMAX);
    float* Rsum = (float*)(smu + AT_RSUM);

    const int h    = blockIdx.y;
    const int q0   = blockIdx.x * 64;
    const int tid  = threadIdx.x;
    const int wid  = tid >> 5;
    const int lane = tid & 31;
    const int g    = lane >> 2;
    const int tg   = lane & 3;
    const int wm   = wid & 3;
    const int wh   = wid >> 2;
    const int ri0  = wm * 16 + g;
    const int ri1  = ri0 + 8;

    const float scale = 0.08838834764831845f;

    for (int i = tid; i < 64 * 32; i += AT_THREADS) {
        const int r  = i >> 5;
        const int c4 = (i & 31) * 4;
        float4 v = *(const float4*)(g_q + ((size_t)(q0 + r) * HEADS + h) * HEAD_DIM + c4);
        uint4 hh;
        hh.x = tf32_rna(v.x * scale);
        hh.y = tf32_rna(v.y * scale);
        hh.z = tf32_rna(v.z * scale);
        hh.w = tf32_rna(v.w * scale);
        *(uint4*)(Qh + r * 132 + c4) = hh;
    }

    float m0 = -INFINITY, m1 = -INFINITY, l0 = 0.f, l1 = 0.f;
    float o[8][4];
    #pragma unroll
    for (int j = 0; j < 8; j++)
        #pragma unroll
        for (int r = 0; r < 4; r++) o[j][r] = 0.f;

    for (int kv0 = 0; kv0 < S_LEN; kv0 += 64) {
        __syncthreads();
        for (int i = tid; i < 64 * 32; i += AT_THREADS) {
            const int r  = i >> 5;
            const int c4 = (i & 31) * 4;
            float4 kv4 = *(const float4*)(g_k + ((size_t)(kv0 + r) * HEADS + h) * HEAD_DIM + c4);
            uint4 t;
            t.x = tf32_rna(kv4.x); t.y = tf32_rna(kv4.y);
            t.z = tf32_rna(kv4.z); t.w = tf32_rna(kv4.w);
            *(uint4*)(Ks + r * 132 + c4) = t;
            float4 vv4 = *(const float4*)(g_v + ((size_t)(kv0 + r) * HEADS + h) * HEAD_DIM + c4);
            uint4 u;
            u.x = tf32_rna(vv4.x); u.y = tf32_rna(vv4.y);
            u.z = tf32_rna(vv4.z); u.w = tf32_rna(vv4.w);
            *(uint4*)(Vs + r * 136 + c4) = u;
        }
        __syncthreads();

        // ---- S = Q K^T ----
        float s[4][4];
        #pragma unroll
        for (int j = 0; j < 4; j++)
            #pragma unroll
            for (int r = 0; r < 4; r++) s[j][r] = 0.f;

        #pragma unroll
        for (int kk8 = 0; kk8 < 16; kk8++) {
            const int kk = kk8 * 8;
            uint32_t ah[4];
            ah[0] = Qh[ri0 * 132 + kk + tg];
            ah[1] = Qh[ri1 * 132 + kk + tg];
            ah[2] = Qh[ri0 * 132 + kk + tg + 4];
            ah[3] = Qh[ri1 * 132 + kk + tg + 4];
            #pragma unroll
            for (int j = 0; j < 4; j++) {
                const int nv = wh * 32 + j * 8 + g;
                uint32_t bb[2];
                bb[0] = Ks[nv * 132 + kk + tg];
                bb[1] = Ks[nv * 132 + kk + tg + 4];
                mma_tf32(s[j], ah, bb);
            }
        }

        // ---- row max ----
        float mx0 = fmaxf(fmaxf(s[0][0], s[0][1]), fmaxf(s[1][0], s[1][1]));
        mx0 = fmaxf(mx0, fmaxf(fmaxf(s[2][0], s[2][1]), fmaxf(s[3][0], s[3][1])));
        float mx1 = fmaxf(fmaxf(s[0][2], s[0][3]), fmaxf(s[1][2], s[1][3]));
        mx1 = fmaxf(mx1, fmaxf(fmaxf(s[2][2], s[2][3]), fmaxf(s[3][2], s[3][3])));
        mx0 = fmaxf(mx0, __shfl_xor_sync(0xffffffffu, mx0, 1));
        mx0 = fmaxf(mx0, __shfl_xor_sync(0xffffffffu, mx0, 2));
        mx1 = fmaxf(mx1, __shfl_xor_sync(0xffffffffu, mx1, 1));
        mx1 = fmaxf(mx1, __shfl_xor_sync(0xffffffffu, mx1, 2));
        if (tg == 0) {
            Rmax[wh * 64 + ri0] = mx0;
            Rmax[wh * 64 + ri1] = mx1;
        }
        __syncthreads();
        const float mn0 = fmaxf(m0, fmaxf(Rmax[ri0], Rmax[64 + ri0]));
        const float mn1 = fmaxf(m1, fmaxf(Rmax[ri1], Rmax[64 + ri1]));
        const float alpha0 = __expf(m0 - mn0);
        const float alpha1 = __expf(m1 - mn1);

        // ---- p = exp(s - m), stage tf32 P, partial row sums ----
        float sum0 = 0.f, sum1 = 0.f;
        #pragma unroll
        for (int j = 0; j < 4; j++) {
            const int col = wh * 32 + j * 8 + 2 * tg;
            const float p0 = __expf(s[j][0] - mn0);
            const float p1 = __expf(s[j][1] - mn0);
            const float p2 = __expf(s[j][2] - mn1);
            const float p3 = __expf(s[j][3] - mn1);
            sum0 += p0 + p1;
            sum1 += p2 + p3;
            Ph[ri0 * 68 + col]     = tf32_rna(p0);
            Ph[ri0 * 68 + col + 1] = tf32_rna(p1);
            Ph[ri1 * 68 + col]     = tf32_rna(p2);
            Ph[ri1 * 68 + col + 1] = tf32_rna(p3);
        }
        sum0 += __shfl_xor_sync(0xffffffffu, sum0, 1);
        sum0 += __shfl_xor_sync(0xffffffffu, sum0, 2);
        sum1 += __shfl_xor_sync(0xffffffffu, sum1, 1);
        sum1 += __shfl_xor_sync(0xffffffffu, sum1, 2);
        if (tg == 0) {
            Rsum[wh * 64 + ri0] = sum0;
            Rsum[wh * 64 + ri1] = sum1;
        }
        __syncthreads();
        l0 = l0 * alpha0 + Rsum[ri0] + Rsum[64 + ri0];
        l1 = l1 * alpha1 + Rsum[ri1] + Rsum[64 + ri1];
        m0 = mn0; m1 = mn1;

        #pragma unroll
        for (int j = 0; j < 8; j++) {
            o[j][0] *= alpha0; o[j][1] *= alpha0;
            o[j][2] *= alpha1; o[j][3] *= alpha1;
        }

        // ---- O += P V ----
        #pragma unroll
        for (int kk8 = 0; kk8 < 8; kk8++) {
            const int kk = kk8 * 8;
            uint32_t ah[4];
            ah[0] = Ph[ri0 * 68 + kk + tg];
            ah[1] = Ph[ri1 * 68 + kk + tg];
            ah[2] = Ph[ri0 * 68 + kk + tg + 4];
            ah[3] = Ph[ri1 * 68 + kk + tg + 4];
            #pragma unroll
            for (int j = 0; j < 8; j++) {
                const int nd = wh * 64 + j * 8 + g;
                uint32_t bb[2];
                bb[0] = Vs[(kk + tg)     * 136 + nd];
                bb[1] = Vs[(kk + tg + 4) * 136 + nd];
                mma_tf32(o[j], ah, bb);
            }
        }
    }

    const float inv0 = 1.f / l0;
    const float inv1 = 1.f / l1;
    #pragma unroll
    for (int j = 0; j < 8; j++) {
        const int d = h * HEAD_DIM + wh * 64 + j * 8 + 2 * tg;
        *(float2*)(out + (size_t)(q0 + ri0) * DIM + d) =
            make_float2(o[j][0] * inv0, o[j][1] * inv0);
        *(float2*)(out + (size_t)(q0 + ri1) * DIM + d) =
            make_float2(o[j][2] * inv1, o[j][3] * inv1);
    }
}

// ---------------------------------------------------------------------------
extern "C" void kernel_launch(void* const* d_in, const int* in_sizes, int n_in,
                              void* d_out, int out_size)
{
    (void)in_sizes; (void)n_in; (void)out_size;
    const float* x  = (const float*)d_in[0];
    const float* cs = (const float*)d_in[1];
    const float* sn = (const float*)d_in[2];
    const float* Wq = (const float*)d_in[3];
    const float* bq = (const float*)d_in[4];
    const float* Wk = (const float*)d_in[5];
    const float* bk = (const float*)d_in[6];
    const float* Wv = (const float*)d_in[7];
    const float* bv = (const float*)d_in[8];
    const float* gq = (const float*)d_in[9];
    const float* gk = (const float*)d_in[10];
    float* out = (float*)d_out;

    // Stage 1: QKV projections (mma.sync tf32, 128x256 CTA, 16 warps)
    cudaFuncSetAttribute(qkv_mma_kernel, cudaFuncAttributeMaxDynamicSharedMemorySize,
                         QSMEM_BYTES);
    dim3 gg(DIM / 256, S_LEN / 128, 3);
    qkv_mma_kernel<<<gg, QTHREADS, QSMEM_BYTES>>>(x, Wq, bq, Wk, bk, Wv, bv);

    // Stage 2: RMSNorm + RoPE on q, k
    const int warps  = 2 * S_LEN * HEADS;
    const int thr    = 256;
    const int blocks = (warps * 32 + thr - 1) / thr;
    rms_rope_kernel<<<blocks, thr>>>(cs, sn, gq, gk);

    // Stage 3: attention (mma.sync tf32, single-pass)
    cudaFuncSetAttribute(attn_mma_kernel, cudaFuncAttributeMaxDynamicSharedMemorySize,
                         AT_SMEM_BYTES);
    dim3 ga(S_LEN / 64, HEADS);
    attn_mma_kernel<<<ga, AT_THREADS, AT_SMEM_BYTES>>>(out);
}

// round 14
// speedup vs baseline: 1.1993x; 1.0213x over previous
#include <cuda_runtime.h>
#include <math.h>
#include <stdint.h>

#define S_LEN    2048
#define DIM      3072
#define HEADS    24
#define HEAD_DIM 128

// Scratch (no cudaMalloc allowed): q, k, v post-projection
__device__ float g_q[S_LEN * DIM];
__device__ float g_k[S_LEN * DIM];
__device__ float g_v[S_LEN * DIM];

// ---- helpers -------------------------------------------------------------
__device__ __forceinline__ uint32_t tf32_rna(float x) {
    uint32_t r;
    asm("cvt.rna.tf32.f32 %0, %1;" : "=r"(r) : "f"(x));
    return r;
}
__device__ __forceinline__ void mma_tf32(float c[4], const uint32_t a[4], const uint32_t b[2]) {
    asm volatile(
        "mma.sync.aligned.m16n8k8.row.col.f32.tf32.tf32.f32 "
        "{%0,%1,%2,%3}, {%4,%5,%6,%7}, {%8,%9}, {%0,%1,%2,%3};"
        : "+f"(c[0]), "+f"(c[1]), "+f"(c[2]), "+f"(c[3])
        : "r"(a[0]), "r"(a[1]), "r"(a[2]), "r"(a[3]), "r"(b[0]), "r"(b[1]));
}
__device__ __forceinline__ void cp_async16(uint32_t smem_dst, const void* gsrc) {
    asm volatile("cp.async.cg.shared.global [%0], [%1], 16;"
                 :: "r"(smem_dst), "l"(gsrc));
}
__device__ __forceinline__ void cp_commit() {
    asm volatile("cp.async.commit_group;" ::: "memory");
}
template <int N>
__device__ __forceinline__ void cp_wait() {
    asm volatile("cp.async.wait_group %0;" :: "n"(N) : "memory");
}

// ===========================================================================
// Stage 1: QKV projection via mma.sync tf32 (round-12 validated: 997us).
// CTA tile 128x256, 512 threads, 16 warps (4m x 4n), warp tile 32x64.
// K-chunk 32, 3-stage cp.async pipeline, one __syncthreads per chunk.
// ===========================================================================
#define QTHREADS 512
#define QA_STRIDE 36
#define QB_STRIDE 264
#define QA_FLOATS (128 * QA_STRIDE)              // 4608
#define QB_FLOATS (32 * QB_STRIDE)               // 8448
#define QBUF_FLOATS (QA_FLOATS + QB_FLOATS)      // 13056
#define QSTAGES 3
#define QSMEM_BYTES (QSTAGES * QBUF_FLOATS * 4)  // 156672
#define NCHUNK (DIM / 32)                        // 96

__global__ __launch_bounds__(QTHREADS, 1) void qkv_mma_kernel(
    const float* __restrict__ x,
    const float* __restrict__ Wq, const float* __restrict__ bq,
    const float* __restrict__ Wk, const float* __restrict__ bk,
    const float* __restrict__ Wv, const float* __restrict__ bv)
{
    extern __shared__ float smem[];
    const float* W; const float* bias; float* out;
    if (blockIdx.z == 0)      { W = Wq; bias = bq; out = g_q; }
    else if (blockIdx.z == 1) { W = Wk; bias = bk; out = g_k; }
    else                      { W = Wv; bias = bv; out = g_v; }

    const int tid  = threadIdx.x;
    const int wid  = tid >> 5;
    const int lane = tid & 31;
    const int g    = lane >> 2;
    const int tg   = lane & 3;
    const int wm   = wid >> 2;       // 0..3 -> rows 32*wm
    const int wn   = wid & 3;        // 0..3 -> cols 64*wn
    const int row0 = blockIdx.y * 128;
    const int col0 = blockIdx.x * 256;

    const int arow = tid >> 2;              // 0..127
    const int acol = (tid & 3) * 8;         // 0/8/16/24
    const int brow = tid >> 4;              // 0..31
    const int bcol = (tid & 15) * 16;       // 0..240

    const float* xA = x + (size_t)(row0 + arow) * DIM + acol;
    const float* wB = W + (size_t)brow * DIM + col0 + bcol;

    const uint32_t smem_u32 = (uint32_t)__cvta_generic_to_shared(smem);
    auto As = [&](int b) -> uint32_t { return smem_u32 + (uint32_t)(b * QBUF_FLOATS) * 4u; };
    auto Bs = [&](int b) -> uint32_t { return As(b) + QA_FLOATS * 4u; };

    auto issue_chunk = [&](int c, int b) {
        const float* asrc = xA + c * 32;
        const uint32_t adst = As(b) + (uint32_t)(arow * QA_STRIDE + acol) * 4u;
        #pragma unroll
        for (int j = 0; j < 2; j++)
            cp_async16(adst + j * 16u, asrc + j * 4);
        const float* bsrc = wB + (size_t)(c * 32) * DIM;
        const uint32_t bdst = Bs(b) + (uint32_t)(brow * QB_STRIDE + bcol) * 4u;
        #pragma unroll
        for (int j = 0; j < 4; j++)
            cp_async16(bdst + j * 16u, bsrc + j * 4);
    };

    float acc[2][8][4];
    #pragma unroll
    for (int i = 0; i < 2; i++)
        #pragma unroll
        for (int j = 0; j < 8; j++)
            #pragma unroll
            for (int r = 0; r < 4; r++) acc[i][j][r] = 0.f;

    issue_chunk(0, 0); cp_commit();
    issue_chunk(1, 1); cp_commit();

    for (int c = 0; c < NCHUNK; c++) {
        const int b = c % QSTAGES;
        cp_wait<1>();
        __syncthreads();
        if (c + 2 < NCHUNK) issue_chunk(c + 2, (c + 2) % QSTAGES);
        cp_commit();

        const float* Ap = smem + (size_t)b * QBUF_FLOATS;
        const float* Bp = smem + (size_t)b * QBUF_FLOATS + QA_FLOATS;

        #pragma unroll
        for (int kk8 = 0; kk8 < 4; kk8++) {
            const int kk = kk8 * 8;
            uint32_t bb[8][2];
            #pragma unroll
            for (int j = 0; j < 8; j++) {
                const int n = wn * 64 + j * 8 + g;
                bb[j][0] = tf32_rna(Bp[(kk + tg)     * QB_STRIDE + n]);
                bb[j][1] = tf32_rna(Bp[(kk + tg + 4) * QB_STRIDE + n]);
            }
            #pragma unroll
            for (int i = 0; i < 2; i++) {
                const int r = wm * 32 + i * 16 + g;
                uint32_t ah[4];
                ah[0] = tf32_rna(Ap[(r)     * QA_STRIDE + kk + tg]);
                ah[1] = tf32_rna(Ap[(r + 8) * QA_STRIDE + kk + tg]);
                ah[2] = tf32_rna(Ap[(r)     * QA_STRIDE + kk + tg + 4]);
                ah[3] = tf32_rna(Ap[(r + 8) * QA_STRIDE + kk + tg + 4]);
                #pragma unroll
                for (int j = 0; j < 8; j++)
                    mma_tf32(acc[i][j], ah, bb[j]);
            }
        }
    }

    #pragma unroll
    for (int j = 0; j < 8; j++) {
        const int n = col0 + wn * 64 + j * 8 + 2 * tg;
        const float2 bb = *(const float2*)(bias + n);
        #pragma unroll
        for (int i = 0; i < 2; i++) {
            const int r = row0 + wm * 32 + i * 16 + g;
            float2 o0 = make_float2(acc[i][j][0] + bb.x, acc[i][j][1] + bb.y);
            float2 o1 = make_float2(acc[i][j][2] + bb.x, acc[i][j][3] + bb.y);
            *(float2*)(out + (size_t)r * DIM + n)       = o0;
            *(float2*)(out + (size_t)(r + 8) * DIM + n) = o1;
        }
    }
}

// ---------------------------------------------------------------------------
// Stage 2: per-head RMSNorm + RoPE applied in place to g_q and g_k.
// ---------------------------------------------------------------------------
__global__ __launch_bounds__(256) void rms_rope_kernel(
    const float* __restrict__ cosb, const float* __restrict__ sinb,
    const float* __restrict__ gq, const float* __restrict__ gk)
{
    const int gw   = (blockIdx.x * blockDim.x + threadIdx.x) >> 5;
    const int lane = threadIdx.x & 31;
    const int rows = S_LEN * HEADS;
    if (gw >= 2 * rows) return;

    const int t  = (gw >= rows) ? 1 : 0;
    const int rr = t ? (gw - rows) : gw;
    const int s  = rr / HEADS;

    float* ptr = (t ? g_k : g_q) + (size_t)rr * HEAD_DIM;
    const float* g = t ? gk : gq;

    float4 vx = *(float4*)(ptr + lane * 4);
    float ss = vx.x * vx.x + vx.y * vx.y + vx.z * vx.z + vx.w * vx.w;
    #pragma unroll
    for (int o = 16; o > 0; o >>= 1) ss += __shfl_xor_sync(0xffffffffu, ss, o);
    const float rnorm = rsqrtf(ss * (1.0f / HEAD_DIM) + 1e-6f);

    float4 gg = *(const float4*)(g + lane * 4);
    vx.x *= rnorm * gg.x; vx.y *= rnorm * gg.y;
    vx.z *= rnorm * gg.z; vx.w *= rnorm * gg.w;

    float4 c  = *(const float4*)(cosb + (size_t)s * HEAD_DIM + lane * 4);
    float4 sn = *(const float4*)(sinb + (size_t)s * HEAD_DIM + lane * 4);
    float4 o;
    o.x = vx.x * c.x - vx.y * sn.x;
    o.y = vx.y * c.y + vx.x * sn.y;
    o.z = vx.z * c.z - vx.w * sn.z;
    o.w = vx.w * c.w + vx.z * sn.w;
    *(float4*)(ptr + lane * 4) = o;
}

// ===========================================================================
// Stage 3: flash attention on mma.sync tf32, single-pass tf32.
// CTA: 128 q-rows x 1 head, 512 threads, 16 warps = (wm 0-7 rowblock16,
// wh 0-1 col-half) -> 4 warps/SMSP (round-12 lesson applied to attention).
// K/V tiles (64 kv rows) amortized over 128 q-rows: K/V traffic halved.
// Strides: Q 132, K 132, V 136, P 68 — all conflict-free (validated).
// ===========================================================================
#define AT_THREADS 512
#define AT_QH 0
#define AT_KS (AT_QH + 128*132)
#define AT_VS (AT_KS + 64*132)
#define AT_PH (AT_VS + 64*136)
#define AT_RMAX (AT_PH + 128*68)
#define AT_RSUM (AT_RMAX + 256)
#define AT_TOTAL (AT_RSUM + 256)
#define AT_SMEM_BYTES (AT_TOTAL * 4)             // 173056

__global__ __launch_bounds__(AT_THREADS, 1) void attn_mma_kernel(float* __restrict__ out)
{
    extern __shared__ uint32_t smu[];
    uint32_t* Qh = smu + AT_QH;
    uint32_t* Ks = smu + AT_KS;
    uint32_t* Vs = smu + AT_VS;
    uint32_t* Ph = smu + AT_PH;
    float* Rmax = (float*)(smu + AT_RMAX);
    float* Rsum = (float*)(smu + AT_RSUM);

    const int h    = blockIdx.y;
    const int q0   = blockIdx.x * 128;
    const int tid  = threadIdx.x;
    const int wid  = tid >> 5;
    const int lane = tid & 31;
    const int g    = lane >> 2;
    const int tg   = lane & 3;
    const int wm   = wid >> 1;      // 0..7 -> q row-block (16 rows)
    const int wh   = wid & 1;       // column half
    const int ri0  = wm * 16 + g;   // 0..127
    const int ri1  = ri0 + 8;

    const float scale = 0.08838834764831845f;

    // ---- load Q tile (128 rows, scaled, tf32) ----
    for (int i = tid; i < 128 * 32; i += AT_THREADS) {
        const int r  = i >> 5;
        const int c4 = (i & 31) * 4;
        float4 v = *(const float4*)(g_q + ((size_t)(q0 + r) * HEADS + h) * HEAD_DIM + c4);
        uint4 hh;
        hh.x = tf32_rna(v.x * scale);
        hh.y = tf32_rna(v.y * scale);
        hh.z = tf32_rna(v.z * scale);
        hh.w = tf32_rna(v.w * scale);
        *(uint4*)(Qh + r * 132 + c4) = hh;
    }

    float m0 = -INFINITY, m1 = -INFINITY, l0 = 0.f, l1 = 0.f;
    float o[8][4];
    #pragma unroll
    for (int j = 0; j < 8; j++)
        #pragma unroll
        for (int r = 0; r < 4; r++) o[j][r] = 0.f;

    for (int kv0 = 0; kv0 < S_LEN; kv0 += 64) {
        __syncthreads();
        for (int i = tid; i < 64 * 32; i += AT_THREADS) {
            const int r  = i >> 5;
            const int c4 = (i & 31) * 4;
            float4 kv4 = *(const float4*)(g_k + ((size_t)(kv0 + r) * HEADS + h) * HEAD_DIM + c4);
            uint4 t;
            t.x = tf32_rna(kv4.x); t.y = tf32_rna(kv4.y);
            t.z = tf32_rna(kv4.z); t.w = tf32_rna(kv4.w);
            *(uint4*)(Ks + r * 132 + c4) = t;
            float4 vv4 = *(const float4*)(g_v + ((size_t)(kv0 + r) * HEADS + h) * HEAD_DIM + c4);
            uint4 u;
            u.x = tf32_rna(vv4.x); u.y = tf32_rna(vv4.y);
            u.z = tf32_rna(vv4.z); u.w = tf32_rna(vv4.w);
            *(uint4*)(Vs + r * 136 + c4) = u;
        }
        __syncthreads();

        // ---- S = Q K^T ----
        float s[4][4];
        #pragma unroll
        for (int j = 0; j < 4; j++)
            #pragma unroll
            for (int r = 0; r < 4; r++) s[j][r] = 0.f;

        #pragma unroll
        for (int kk8 = 0; kk8 < 16; kk8++) {
            const int kk = kk8 * 8;
            uint32_t ah[4];
            ah[0] = Qh[ri0 * 132 + kk + tg];
            ah[1] = Qh[ri1 * 132 + kk + tg];
            ah[2] = Qh[ri0 * 132 + kk + tg + 4];
            ah[3] = Qh[ri1 * 132 + kk + tg + 4];
            #pragma unroll
            for (int j = 0; j < 4; j++) {
                const int nv = wh * 32 + j * 8 + g;
                uint32_t bb[2];
                bb[0] = Ks[nv * 132 + kk + tg];
                bb[1] = Ks[nv * 132 + kk + tg + 4];
                mma_tf32(s[j], ah, bb);
            }
        }

        // ---- row max (quad reduce + cross-half via smem) ----
        float mx0 = fmaxf(fmaxf(s[0][0], s[0][1]), fmaxf(s[1][0], s[1][1]));
        mx0 = fmaxf(mx0, fmaxf(fmaxf(s[2][0], s[2][1]), fmaxf(s[3][0], s[3][1])));
        float mx1 = fmaxf(fmaxf(s[0][2], s[0][3]), fmaxf(s[1][2], s[1][3]));
        mx1 = fmaxf(mx1, fmaxf(fmaxf(s[2][2], s[2][3]), fmaxf(s[3][2], s[3][3])));
        mx0 = fmaxf(mx0, __shfl_xor_sync(0xffffffffu, mx0, 1));
        mx0 = fmaxf(mx0, __shfl_xor_sync(0xffffffffu, mx0, 2));
        mx1 = fmaxf(mx1, __shfl_xor_sync(0xffffffffu, mx1, 1));
        mx1 = fmaxf(mx1, __shfl_xor_sync(0xffffffffu, mx1, 2));
        if (tg == 0) {
            Rmax[wh * 128 + ri0] = mx0;
            Rmax[wh * 128 + ri1] = mx1;
        }
        __syncthreads();
        const float mn0 = fmaxf(m0, fmaxf(Rmax[ri0], Rmax[128 + ri0]));
        const float mn1 = fmaxf(m1, fmaxf(Rmax[ri1], Rmax[128 + ri1]));
        const float alpha0 = __expf(m0 - mn0);
        const float alpha1 = __expf(m1 - mn1);

        // ---- p = exp(s - m), stage tf32 P, partial row sums ----
        float sum0 = 0.f, sum1 = 0.f;
        #pragma unroll
        for (int j = 0; j < 4; j++) {
            const int col = wh * 32 + j * 8 + 2 * tg;
            const float p0 = __expf(s[j][0] - mn0);
            const float p1 = __expf(s[j][1] - mn0);
            const float p2 = __expf(s[j][2] - mn1);
            const float p3 = __expf(s[j][3] - mn1);
            sum0 += p0 + p1;
            sum1 += p2 + p3;
            Ph[ri0 * 68 + col]     = tf32_rna(p0);
            Ph[ri0 * 68 + col + 1] = tf32_rna(p1);
            Ph[ri1 * 68 + col]     = tf32_rna(p2);
            Ph[ri1 * 68 + col + 1] = tf32_rna(p3);
        }
        sum0 += __shfl_xor_sync(0xffffffffu, sum0, 1);
        sum0 += __shfl_xor_sync(0xffffffffu, sum0, 2);
        sum1 += __shfl_xor_sync(0xffffffffu, sum1, 1);
        sum1 += __shfl_xor_sync(0xffffffffu, sum1, 2);
        if (tg == 0) {
            Rsum[wh * 128 + ri0] = sum0;
            Rsum[wh * 128 + ri1] = sum1;
        }
        __syncthreads();
        l0 = l0 * alpha0 + Rsum[ri0] + Rsum[128 + ri0];
        l1 = l1 * alpha1 + Rsum[ri1] + Rsum[128 + ri1];
        m0 = mn0; m1 = mn1;

        #pragma unroll
        for (int j = 0; j < 8; j++) {
            o[j][0] *= alpha0; o[j][1] *= alpha0;
            o[j][2] *= alpha1; o[j][3] *= alpha1;
        }

        // ---- O += P V ----
        #pragma unroll
        for (int kk8 = 0; kk8 < 8; kk8++) {
            const int kk = kk8 * 8;
            uint32_t ah[4];
            ah[0] = Ph[ri0 * 68 + kk + tg];
            ah[1] = Ph[ri1 * 68 + kk + tg];
            ah[2] = Ph[ri0 * 68 + kk + tg + 4];
            ah[3] = Ph[ri1 * 68 + kk + tg + 4];
            #pragma unroll
            for (int j = 0; j < 8; j++) {
                const int nd = wh * 64 + j * 8 + g;
                uint32_t bb[2];
                bb[0] = Vs[(kk + tg)     * 136 + nd];
                bb[1] = Vs[(kk + tg + 4) * 136 + nd];
                mma_tf32(o[j], ah, bb);
            }
        }
    }

    const float inv0 = 1.f / l0;
    const float inv1 = 1.f / l1;
    #pragma unroll
    for (int j = 0; j < 8; j++) {
        const int d = h * HEAD_DIM + wh * 64 + j * 8 + 2 * tg;
        *(float2*)(out + (size_t)(q0 + ri0) * DIM + d) =
            make_float2(o[j][0] * inv0, o[j][1] * inv0);
        *(float2*)(out + (size_t)(q0 + ri1) * DIM + d) =
            make_float2(o[j][2] * inv1, o[j][3] * inv1);
    }
}

// ---------------------------------------------------------------------------
extern "C" void kernel_launch(void* const* d_in, const int* in_sizes, int n_in,
                              void* d_out, int out_size)
{
    (void)in_sizes; (void)n_in; (void)out_size;
    const float* x  = (const float*)d_in[0];
    const float* cs = (const float*)d_in[1];
    const float* sn = (const float*)d_in[2];
    const float* Wq = (const float*)d_in[3];
    const float* bq = (const float*)d_in[4];
    const float* Wk = (const float*)d_in[5];
    const float* bk = (const float*)d_in[6];
    const float* Wv = (const float*)d_in[7];
    const float* bv = (const float*)d_in[8];
    const float* gq = (const float*)d_in[9];
    const float* gk = (const float*)d_in[10];
    float* out = (float*)d_out;

    // Stage 1: QKV projections (mma.sync tf32, 128x256 CTA, 16 warps)
    cudaFuncSetAttribute(qkv_mma_kernel, cudaFuncAttributeMaxDynamicSharedMemorySize,
                         QSMEM_BYTES);
    dim3 gg(DIM / 256, S_LEN / 128, 3);
    qkv_mma_kernel<<<gg, QTHREADS, QSMEM_BYTES>>>(x, Wq, bq, Wk, bk, Wv, bv);

    // Stage 2: RMSNorm + RoPE on q, k
    const int warps  = 2 * S_LEN * HEADS;
    const int thr    = 256;
    const int blocks = (warps * 32 + thr - 1) / thr;
    rms_rope_kernel<<<blocks, thr>>>(cs, sn, gq, gk);

    // Stage 3: attention (mma.sync tf32, 128 q-rows, 16 warps)
    cudaFuncSetAttribute(attn_mma_kernel, cudaFuncAttributeMaxDynamicSharedMemorySize,
                         AT_SMEM_BYTES);
    dim3 ga(S_LEN / 128, HEADS);
    attn_mma_kernel<<<ga, AT_THREADS, AT_SMEM_BYTES>>>(out);
}

// round 15
// speedup vs baseline: 1.2514x; 1.0434x over previous
#include <cuda_runtime.h>
#include <math.h>
#include <stdint.h>

#define S_LEN    2048
#define DIM      3072
#define HEADS    24
#define HEAD_DIM 128

// Scratch (no cudaMalloc allowed)
__device__ float g_q[S_LEN * DIM];
__device__ float g_k[S_LEN * DIM];
__device__ float g_v[S_LEN * DIM];
// tf32-pre-rounded copies of x and the three weight matrices
__device__ float g_xc[S_LEN * DIM];
__device__ float g_wc[3 * DIM * DIM];

// ---- helpers -------------------------------------------------------------
__device__ __forceinline__ uint32_t tf32_rna(float x) {
    uint32_t r;
    asm("cvt.rna.tf32.f32 %0, %1;" : "=r"(r) : "f"(x));
    return r;
}
__device__ __forceinline__ void mma_tf32(float c[4], const uint32_t a[4], const uint32_t b[2]) {
    asm volatile(
        "mma.sync.aligned.m16n8k8.row.col.f32.tf32.tf32.f32 "
        "{%0,%1,%2,%3}, {%4,%5,%6,%7}, {%8,%9}, {%0,%1,%2,%3};"
        : "+f"(c[0]), "+f"(c[1]), "+f"(c[2]), "+f"(c[3])
        : "r"(a[0]), "r"(a[1]), "r"(a[2]), "r"(a[3]), "r"(b[0]), "r"(b[1]));
}
__device__ __forceinline__ void cp_async16(uint32_t smem_dst, const void* gsrc) {
    asm volatile("cp.async.cg.shared.global [%0], [%1], 16;"
                 :: "r"(smem_dst), "l"(gsrc));
}
__device__ __forceinline__ void cp_commit() {
    asm volatile("cp.async.commit_group;" ::: "memory");
}
template <int N>
__device__ __forceinline__ void cp_wait() {
    asm volatile("cp.async.wait_group %0;" :: "n"(N) : "memory");
}

// ===========================================================================
// Stage 0: one-shot tf32 rounding of x and W into device scratch.
// Grid-stride float4; pure streaming (~276 MB -> ~60-90us).
// ===========================================================================
#define XN (S_LEN * DIM)          // 6291456
#define WN (DIM * DIM)            // 9437184

__global__ __launch_bounds__(256) void tf32_prep_kernel(
    const float* __restrict__ x,
    const float* __restrict__ Wq,
    const float* __restrict__ Wk,
    const float* __restrict__ Wv)
{
    const int total4 = (XN + 3 * WN) / 4;
    for (int i = blockIdx.x * blockDim.x + threadIdx.x; i < total4;
         i += gridDim.x * blockDim.x) {
        const float* src;
        float* dst;
        int idx = i * 4;
        if (idx < XN)                  { src = x  + idx;               dst = g_xc + idx; }
        else if (idx < XN + WN)        { src = Wq + (idx - XN);        dst = g_wc + (idx - XN); }
        else if (idx < XN + 2 * WN)    { src = Wk + (idx - XN - WN);   dst = g_wc + (idx - XN); }
        else                           { src = Wv + (idx - XN - 2*WN); dst = g_wc + (idx - XN); }
        float4 v = *(const float4*)src;
        uint4 h;
        h.x = tf32_rna(v.x); h.y = tf32_rna(v.y);
        h.z = tf32_rna(v.z); h.w = tf32_rna(v.w);
        *(uint4*)dst = h;
    }
}

// ===========================================================================
// Stage 1: QKV projection via mma.sync tf32 on pre-rounded inputs.
// CTA tile 128x256, 512 threads, 16 warps (4m x 4n), warp tile 32x64.
// K-chunk 32, 3-stage cp.async pipeline, one __syncthreads per chunk.
// Hot loop: pure LDS + MMA (cvt hoisted into tf32_prep_kernel).
// ===========================================================================
#define QTHREADS 512
#define QA_STRIDE 36
#define QB_STRIDE 264
#define QA_FLOATS (128 * QA_STRIDE)              // 4608
#define QB_FLOATS (32 * QB_STRIDE)               // 8448
#define QBUF_FLOATS (QA_FLOATS + QB_FLOATS)      // 13056
#define QSTAGES 3
#define QSMEM_BYTES (QSTAGES * QBUF_FLOATS * 4)  // 156672
#define NCHUNK (DIM / 32)                        // 96

__global__ __launch_bounds__(QTHREADS, 1) void qkv_mma_kernel(
    const float* __restrict__ bq,
    const float* __restrict__ bk,
    const float* __restrict__ bv)
{
    extern __shared__ float smem[];
    const float* W = g_wc + (size_t)blockIdx.z * WN;
    const float* bias; float* out;
    if (blockIdx.z == 0)      { bias = bq; out = g_q; }
    else if (blockIdx.z == 1) { bias = bk; out = g_k; }
    else                      { bias = bv; out = g_v; }

    const int tid  = threadIdx.x;
    const int wid  = tid >> 5;
    const int lane = tid & 31;
    const int g    = lane >> 2;
    const int tg   = lane & 3;
    const int wm   = wid >> 2;       // 0..3 -> rows 32*wm
    const int wn   = wid & 3;        // 0..3 -> cols 64*wn
    const int row0 = blockIdx.y * 128;
    const int col0 = blockIdx.x * 256;

    const int arow = tid >> 2;              // 0..127
    const int acol = (tid & 3) * 8;         // 0/8/16/24
    const int brow = tid >> 4;              // 0..31
    const int bcol = (tid & 15) * 16;       // 0..240

    const float* xA = g_xc + (size_t)(row0 + arow) * DIM + acol;
    const float* wB = W + (size_t)brow * DIM + col0 + bcol;

    const uint32_t smem_u32 = (uint32_t)__cvta_generic_to_shared(smem);
    auto As = [&](int b) -> uint32_t { return smem_u32 + (uint32_t)(b * QBUF_FLOATS) * 4u; };
    auto Bs = [&](int b) -> uint32_t { return As(b) + QA_FLOATS * 4u; };

    auto issue_chunk = [&](int c, int b) {
        const float* asrc = xA + c * 32;
        const uint32_t adst = As(b) + (uint32_t)(arow * QA_STRIDE + acol) * 4u;
        #pragma unroll
        for (int j = 0; j < 2; j++)
            cp_async16(adst + j * 16u, asrc + j * 4);
        const float* bsrc = wB + (size_t)(c * 32) * DIM;
        const uint32_t bdst = Bs(b) + (uint32_t)(brow * QB_STRIDE + bcol) * 4u;
        #pragma unroll
        for (int j = 0; j < 4; j++)
            cp_async16(bdst + j * 16u, bsrc + j * 4);
    };

    float acc[2][8][4];
    #pragma unroll
    for (int i = 0; i < 2; i++)
        #pragma unroll
        for (int j = 0; j < 8; j++)
            #pragma unroll
            for (int r = 0; r < 4; r++) acc[i][j][r] = 0.f;

    issue_chunk(0, 0); cp_commit();
    issue_chunk(1, 1); cp_commit();

    for (int c = 0; c < NCHUNK; c++) {
        const int b = c % QSTAGES;
        cp_wait<1>();
        __syncthreads();
        if (c + 2 < NCHUNK) issue_chunk(c + 2, (c + 2) % QSTAGES);
        cp_commit();

        const uint32_t* Ap = (const uint32_t*)(smem + (size_t)b * QBUF_FLOATS);
        const uint32_t* Bp = (const uint32_t*)(smem + (size_t)b * QBUF_FLOATS + QA_FLOATS);

        #pragma unroll
        for (int kk8 = 0; kk8 < 4; kk8++) {
            const int kk = kk8 * 8;
            uint32_t bb[8][2];
            #pragma unroll
            for (int j = 0; j < 8; j++) {
                const int n = wn * 64 + j * 8 + g;
                bb[j][0] = Bp[(kk + tg)     * QB_STRIDE + n];
                bb[j][1] = Bp[(kk + tg + 4) * QB_STRIDE + n];
            }
            #pragma unroll
            for (int i = 0; i < 2; i++) {
                const int r = wm * 32 + i * 16 + g;
                uint32_t ah[4];
                ah[0] = Ap[(r)     * QA_STRIDE + kk + tg];
                ah[1] = Ap[(r + 8) * QA_STRIDE + kk + tg];
                ah[2] = Ap[(r)     * QA_STRIDE + kk + tg + 4];
                ah[3] = Ap[(r + 8) * QA_STRIDE + kk + tg + 4];
                #pragma unroll
                for (int j = 0; j < 8; j++)
                    mma_tf32(acc[i][j], ah, bb[j]);
            }
        }
    }

    #pragma unroll
    for (int j = 0; j < 8; j++) {
        const int n = col0 + wn * 64 + j * 8 + 2 * tg;
        const float2 bb = *(const float2*)(bias + n);
        #pragma unroll
        for (int i = 0; i < 2; i++) {
            const int r = row0 + wm * 32 + i * 16 + g;
            float2 o0 = make_float2(acc[i][j][0] + bb.x, acc[i][j][1] + bb.y);
            float2 o1 = make_float2(acc[i][j][2] + bb.x, acc[i][j][3] + bb.y);
            *(float2*)(out + (size_t)r * DIM + n)       = o0;
            *(float2*)(out + (size_t)(r + 8) * DIM + n) = o1;
        }
    }
}

// ---------------------------------------------------------------------------
// Stage 2: per-head RMSNorm + RoPE applied in place to g_q and g_k.
// ---------------------------------------------------------------------------
__global__ __launch_bounds__(256) void rms_rope_kernel(
    const float* __restrict__ cosb, const float* __restrict__ sinb,
    const float* __restrict__ gq, const float* __restrict__ gk)
{
    const int gw   = (blockIdx.x * blockDim.x + threadIdx.x) >> 5;
    const int lane = threadIdx.x & 31;
    const int rows = S_LEN * HEADS;
    if (gw >= 2 * rows) return;

    const int t  = (gw >= rows) ? 1 : 0;
    const int rr = t ? (gw - rows) : gw;
    const int s  = rr / HEADS;

    float* ptr = (t ? g_k : g_q) + (size_t)rr * HEAD_DIM;
    const float* g = t ? gk : gq;

    float4 vx = *(float4*)(ptr + lane * 4);
    float ss = vx.x * vx.x + vx.y * vx.y + vx.z * vx.z + vx.w * vx.w;
    #pragma unroll
    for (int o = 16; o > 0; o >>= 1) ss += __shfl_xor_sync(0xffffffffu, ss, o);
    const float rnorm = rsqrtf(ss * (1.0f / HEAD_DIM) + 1e-6f);

    float4 gg = *(const float4*)(g + lane * 4);
    vx.x *= rnorm * gg.x; vx.y *= rnorm * gg.y;
    vx.z *= rnorm * gg.z; vx.w *= rnorm * gg.w;

    float4 c  = *(const float4*)(cosb + (size_t)s * HEAD_DIM + lane * 4);
    float4 sn = *(const float4*)(sinb + (size_t)s * HEAD_DIM + lane * 4);
    float4 o;
    o.x = vx.x * c.x - vx.y * sn.x;
    o.y = vx.y * c.y + vx.x * sn.y;
    o.z = vx.z * c.z - vx.w * sn.z;
    o.w = vx.w * c.w + vx.z * sn.w;
    *(float4*)(ptr + lane * 4) = o;
}

// ===========================================================================
// Stage 3: flash attention on mma.sync tf32, single-pass tf32 (round-14
// validated). CTA: 128 q-rows x 1 head, 512 threads, 16 warps.
// ===========================================================================
#define AT_THREADS 512
#define AT_QH 0
#define AT_KS (AT_QH + 128*132)
#define AT_VS (AT_KS + 64*132)
#define AT_PH (AT_VS + 64*136)
#define AT_RMAX (AT_PH + 128*68)
#define AT_RSUM (AT_RMAX + 256)
#define AT_TOTAL (AT_RSUM + 256)
#define AT_SMEM_BYTES (AT_TOTAL * 4)             // 173056

__global__ __launch_bounds__(AT_THREADS, 1) void attn_mma_kernel(float* __restrict__ out)
{
    extern __shared__ uint32_t smu[];
    uint32_t* Qh = smu + AT_QH;
    uint32_t* Ks = smu + AT_KS;
    uint32_t* Vs = smu + AT_VS;
    uint32_t* Ph = smu + AT_PH;
    float* Rmax = (float*)(smu + AT_RMAX);
    float* Rsum = (float*)(smu + AT_RSUM);

    const int h    = blockIdx.y;
    const int q0   = blockIdx.x * 128;
    const int tid  = threadIdx.x;
    const int wid  = tid >> 5;
    const int lane = tid & 31;
    const int g    = lane >> 2;
    const int tg   = lane & 3;
    const int wm   = wid >> 1;      // 0..7 -> q row-block (16 rows)
    const int wh   = wid & 1;       // column half
    const int ri0  = wm * 16 + g;   // 0..127
    const int ri1  = ri0 + 8;

    const float scale = 0.08838834764831845f;

    for (int i = tid; i < 128 * 32; i += AT_THREADS) {
        const int r  = i >> 5;
        const int c4 = (i & 31) * 4;
        float4 v = *(const float4*)(g_q + ((size_t)(q0 + r) * HEADS + h) * HEAD_DIM + c4);
        uint4 hh;
        hh.x = tf32_rna(v.x * scale);
        hh.y = tf32_rna(v.y * scale);
        hh.z = tf32_rna(v.z * scale);
        hh.w = tf32_rna(v.w * scale);
        *(uint4*)(Qh + r * 132 + c4) = hh;
    }

    float m0 = -INFINITY, m1 = -INFINITY, l0 = 0.f, l1 = 0.f;
    float o[8][4];
    #pragma unroll
    for (int j = 0; j < 8; j++)
        #pragma unroll
        for (int r = 0; r < 4; r++) o[j][r] = 0.f;

    for (int kv0 = 0; kv0 < S_LEN; kv0 += 64) {
        __syncthreads();
        for (int i = tid; i < 64 * 32; i += AT_THREADS) {
            const int r  = i >> 5;
            const int c4 = (i & 31) * 4;
            float4 kv4 = *(const float4*)(g_k + ((size_t)(kv0 + r) * HEADS + h) * HEAD_DIM + c4);
            uint4 t;
            t.x = tf32_rna(kv4.x); t.y = tf32_rna(kv4.y);
            t.z = tf32_rna(kv4.z); t.w = tf32_rna(kv4.w);
            *(uint4*)(Ks + r * 132 + c4) = t;
            float4 vv4 = *(const float4*)(g_v + ((size_t)(kv0 + r) * HEADS + h) * HEAD_DIM + c4);
            uint4 u;
            u.x = tf32_rna(vv4.x); u.y = tf32_rna(vv4.y);
            u.z = tf32_rna(vv4.z); u.w = tf32_rna(vv4.w);
            *(uint4*)(Vs + r * 136 + c4) = u;
        }
        __syncthreads();

        // ---- S = Q K^T ----
        float s[4][4];
        #pragma unroll
        for (int j = 0; j < 4; j++)
            #pragma unroll
            for (int r = 0; r < 4; r++) s[j][r] = 0.f;

        #pragma unroll
        for (int kk8 = 0; kk8 < 16; kk8++) {
            const int kk = kk8 * 8;
            uint32_t ah[4];
            ah[0] = Qh[ri0 * 132 + kk + tg];
            ah[1] = Qh[ri1 * 132 + kk + tg];
            ah[2] = Qh[ri0 * 132 + kk + tg + 4];
            ah[3] = Qh[ri1 * 132 + kk + tg + 4];
            #pragma unroll
            for (int j = 0; j < 4; j++) {
                const int nv = wh * 32 + j * 8 + g;
                uint32_t bb[2];
                bb[0] = Ks[nv * 132 + kk + tg];
                bb[1] = Ks[nv * 132 + kk + tg + 4];
                mma_tf32(s[j], ah, bb);
            }
        }

        // ---- row max (quad reduce + cross-half via smem) ----
        float mx0 = fmaxf(fmaxf(s[0][0], s[0][1]), fmaxf(s[1][0], s[1][1]));
        mx0 = fmaxf(mx0, fmaxf(fmaxf(s[2][0], s[2][1]), fmaxf(s[3][0], s[3][1])));
        float mx1 = fmaxf(fmaxf(s[0][2], s[0][3]), fmaxf(s[1][2], s[1][3]));
        mx1 = fmaxf(mx1, fmaxf(fmaxf(s[2][2], s[2][3]), fmaxf(s[3][2], s[3][3])));
        mx0 = fmaxf(mx0, __shfl_xor_sync(0xffffffffu, mx0, 1));
        mx0 = fmaxf(mx0, __shfl_xor_sync(0xffffffffu, mx0, 2));
        mx1 = fmaxf(mx1, __shfl_xor_sync(0xffffffffu, mx1, 1));
        mx1 = fmaxf(mx1, __shfl_xor_sync(0xffffffffu, mx1, 2));
        if (tg == 0) {
            Rmax[wh * 128 + ri0] = mx0;
            Rmax[wh * 128 + ri1] = mx1;
        }
        __syncthreads();
        const float mn0 = fmaxf(m0, fmaxf(Rmax[ri0], Rmax[128 + ri0]));
        const float mn1 = fmaxf(m1, fmaxf(Rmax[ri1], Rmax[128 + ri1]));
        const float alpha0 = __expf(m0 - mn0);
        const float alpha1 = __expf(m1 - mn1);

        // ---- p = exp(s - m), stage tf32 P, partial row sums ----
        float sum0 = 0.f, sum1 = 0.f;
        #pragma unroll
        for (int j = 0; j < 4; j++) {
            const int col = wh * 32 + j * 8 + 2 * tg;
            const float p0 = __expf(s[j][0] - mn0);
            const float p1 = __expf(s[j][1] - mn0);
            const float p2 = __expf(s[j][2] - mn1);
            const float p3 = __expf(s[j][3] - mn1);
            sum0 += p0 + p1;
            sum1 += p2 + p3;
            Ph[ri0 * 68 + col]     = tf32_rna(p0);
            Ph[ri0 * 68 + col + 1] = tf32_rna(p1);
            Ph[ri1 * 68 + col]     = tf32_rna(p2);
            Ph[ri1 * 68 + col + 1] = tf32_rna(p3);
        }
        sum0 += __shfl_xor_sync(0xffffffffu, sum0, 1);
        sum0 += __shfl_xor_sync(0xffffffffu, sum0, 2);
        sum1 += __shfl_xor_sync(0xffffffffu, sum1, 1);
        sum1 += __shfl_xor_sync(0xffffffffu, sum1, 2);
        if (tg == 0) {
            Rsum[wh * 128 + ri0] = sum0;
            Rsum[wh * 128 + ri1] = sum1;
        }
        __syncthreads();
        l0 = l0 * alpha0 + Rsum[ri0] + Rsum[128 + ri0];
        l1 = l1 * alpha1 + Rsum[ri1] + Rsum[128 + ri1];
        m0 = mn0; m1 = mn1;

        #pragma unroll
        for (int j = 0; j < 8; j++) {
            o[j][0] *= alpha0; o[j][1] *= alpha0;
            o[j][2] *= alpha1; o[j][3] *= alpha1;
        }

        // ---- O += P V ----
        #pragma unroll
        for (int kk8 = 0; kk8 < 8; kk8++) {
            const int kk = kk8 * 8;
            uint32_t ah[4];
            ah[0] = Ph[ri0 * 68 + kk + tg];
            ah[1] = Ph[ri1 * 68 + kk + tg];
            ah[2] = Ph[ri0 * 68 + kk + tg + 4];
            ah[3] = Ph[ri1 * 68 + kk + tg + 4];
            #pragma unroll
            for (int j = 0; j < 8; j++) {
                const int nd = wh * 64 + j * 8 + g;
                uint32_t bb[2];
                bb[0] = Vs[(kk + tg)     * 136 + nd];
                bb[1] = Vs[(kk + tg + 4) * 136 + nd];
                mma_tf32(o[j], ah, bb);
            }
        }
    }

    const float inv0 = 1.f / l0;
    const float inv1 = 1.f / l1;
    #pragma unroll
    for (int j = 0; j < 8; j++) {
        const int d = h * HEAD_DIM + wh * 64 + j * 8 + 2 * tg;
        *(float2*)(out + (size_t)(q0 + ri0) * DIM + d) =
            make_float2(o[j][0] * inv0, o[j][1] * inv0);
        *(float2*)(out + (size_t)(q0 + ri1) * DIM + d) =
            make_float2(o[j][2] * inv1, o[j][3] * inv1);
    }
}

// ---------------------------------------------------------------------------
extern "C" void kernel_launch(void* const* d_in, const int* in_sizes, int n_in,
                              void* d_out, int out_size)
{
    (void)in_sizes; (void)n_in; (void)out_size;
    const float* x  = (const float*)d_in[0];
    const float* cs = (const float*)d_in[1];
    const float* sn = (const float*)d_in[2];
    const float* Wq = (const float*)d_in[3];
    const float* bq = (const float*)d_in[4];
    const float* Wk = (const float*)d_in[5];
    const float* bk = (const float*)d_in[6];
    const float* Wv = (const float*)d_in[7];
    const float* bv = (const float*)d_in[8];
    const float* gq = (const float*)d_in[9];
    const float* gk = (const float*)d_in[10];
    float* out = (float*)d_out;

    // Stage 0: one-shot tf32 rounding of x and W
    tf32_prep_kernel<<<2048, 256>>>(x, Wq, Wk, Wv);

    // Stage 1: QKV projections (mma.sync tf32, pure LDS+MMA hot loop)
    cudaFuncSetAttribute(qkv_mma_kernel, cudaFuncAttributeMaxDynamicSharedMemorySize,
                         QSMEM_BYTES);
    dim3 gg(DIM / 256, S_LEN / 128, 3);
    qkv_mma_kernel<<<gg, QTHREADS, QSMEM_BYTES>>>(bq, bk, bv);

    // Stage 2: RMSNorm + RoPE on q, k
    const int warps  = 2 * S_LEN * HEADS;
    const int thr    = 256;
    const int blocks = (warps * 32 + thr - 1) / thr;
    rms_rope_kernel<<<blocks, thr>>>(cs, sn, gq, gk);

    // Stage 3: attention (mma.sync tf32, 128 q-rows, 16 warps)
    cudaFuncSetAttribute(attn_mma_kernel, cudaFuncAttributeMaxDynamicSharedMemorySize,
                         AT_SMEM_BYTES);
    dim3 ga(S_LEN / 128, HEADS);
    attn_mma_kernel<<<ga, AT_THREADS, AT_SMEM_BYTES>>>(out);
}

// round 16
// speedup vs baseline: 1.3684x; 1.0935x over previous
#include <cuda_runtime.h>
#include <math.h>
#include <stdint.h>

#define S_LEN    2048
#define DIM      3072
#define HEADS    24
#define HEAD_DIM 128

// Scratch (no cudaMalloc allowed)
__device__ float g_q[S_LEN * DIM];
__device__ float g_k[S_LEN * DIM];
__device__ float g_v[S_LEN * DIM];
// tf32-pre-rounded copies of x and the three weight matrices
__device__ float g_xc[S_LEN * DIM];
__device__ float g_wc[3 * DIM * DIM];

// ---- helpers -------------------------------------------------------------
__device__ __forceinline__ uint32_t tf32_rna(float x) {
    uint32_t r;
    asm("cvt.rna.tf32.f32 %0, %1;" : "=r"(r) : "f"(x));
    return r;
}
__device__ __forceinline__ void mma_tf32(float c[4], const uint32_t a[4], const uint32_t b[2]) {
    asm volatile(
        "mma.sync.aligned.m16n8k8.row.col.f32.tf32.tf32.f32 "
        "{%0,%1,%2,%3}, {%4,%5,%6,%7}, {%8,%9}, {%0,%1,%2,%3};"
        : "+f"(c[0]), "+f"(c[1]), "+f"(c[2]), "+f"(c[3])
        : "r"(a[0]), "r"(a[1]), "r"(a[2]), "r"(a[3]), "r"(b[0]), "r"(b[1]));
}
__device__ __forceinline__ void cp_async16(uint32_t smem_dst, const void* gsrc) {
    asm volatile("cp.async.cg.shared.global [%0], [%1], 16;"
                 :: "r"(smem_dst), "l"(gsrc));
}
__device__ __forceinline__ void cp_commit() {
    asm volatile("cp.async.commit_group;" ::: "memory");
}
template <int N>
__device__ __forceinline__ void cp_wait() {
    asm volatile("cp.async.wait_group %0;" :: "n"(N) : "memory");
}

// ===========================================================================
// Stage 0: one-shot tf32 rounding of x and W into device scratch.
// ===========================================================================
#define XN (S_LEN * DIM)          // 6291456
#define WN (DIM * DIM)            // 9437184

__global__ __launch_bounds__(256) void tf32_prep_kernel(
    const float* __restrict__ x,
    const float* __restrict__ Wq,
    const float* __restrict__ Wk,
    const float* __restrict__ Wv)
{
    const int total4 = (XN + 3 * WN) / 4;
    for (int i = blockIdx.x * blockDim.x + threadIdx.x; i < total4;
         i += gridDim.x * blockDim.x) {
        const float* src;
        float* dst;
        int idx = i * 4;
        if (idx < XN)                  { src = x  + idx;               dst = g_xc + idx; }
        else if (idx < XN + WN)        { src = Wq + (idx - XN);        dst = g_wc + (idx - XN); }
        else if (idx < XN + 2 * WN)    { src = Wk + (idx - XN - WN);   dst = g_wc + (idx - XN); }
        else                           { src = Wv + (idx - XN - 2*WN); dst = g_wc + (idx - XN); }
        float4 v = *(const float4*)src;
        uint4 h;
        h.x = tf32_rna(v.x); h.y = tf32_rna(v.y);
        h.z = tf32_rna(v.z); h.w = tf32_rna(v.w);
        *(uint4*)dst = h;
    }
}

// ===========================================================================
// Stage 1: QKV projection via mma.sync tf32 on pre-rounded inputs
// (round-15 validated: ~814us). CTA 128x256, 512 thr, warp tile 32x64,
// K-chunk 32, 3-stage cp.async pipeline, pure LDS+MMA hot loop.
// ===========================================================================
#define QTHREADS 512
#define QA_STRIDE 36
#define QB_STRIDE 264
#define QA_FLOATS (128 * QA_STRIDE)              // 4608
#define QB_FLOATS (32 * QB_STRIDE)               // 8448
#define QBUF_FLOATS (QA_FLOATS + QB_FLOATS)      // 13056
#define QSTAGES 3
#define QSMEM_BYTES (QSTAGES * QBUF_FLOATS * 4)  // 156672
#define NCHUNK (DIM / 32)                        // 96

__global__ __launch_bounds__(QTHREADS, 1) void qkv_mma_kernel(
    const float* __restrict__ bq,
    const float* __restrict__ bk,
    const float* __restrict__ bv)
{
    extern __shared__ float smem[];
    const float* W = g_wc + (size_t)blockIdx.z * WN;
    const float* bias; float* out;
    if (blockIdx.z == 0)      { bias = bq; out = g_q; }
    else if (blockIdx.z == 1) { bias = bk; out = g_k; }
    else                      { bias = bv; out = g_v; }

    const int tid  = threadIdx.x;
    const int wid  = tid >> 5;
    const int lane = tid & 31;
    const int g    = lane >> 2;
    const int tg   = lane & 3;
    const int wm   = wid >> 2;
    const int wn   = wid & 3;
    const int row0 = blockIdx.y * 128;
    const int col0 = blockIdx.x * 256;

    const int arow = tid >> 2;
    const int acol = (tid & 3) * 8;
    const int brow = tid >> 4;
    const int bcol = (tid & 15) * 16;

    const float* xA = g_xc + (size_t)(row0 + arow) * DIM + acol;
    const float* wB = W + (size_t)brow * DIM + col0 + bcol;

    const uint32_t smem_u32 = (uint32_t)__cvta_generic_to_shared(smem);
    auto As = [&](int b) -> uint32_t { return smem_u32 + (uint32_t)(b * QBUF_FLOATS) * 4u; };
    auto Bs = [&](int b) -> uint32_t { return As(b) + QA_FLOATS * 4u; };

    auto issue_chunk = [&](int c, int b) {
        const float* asrc = xA + c * 32;
        const uint32_t adst = As(b) + (uint32_t)(arow * QA_STRIDE + acol) * 4u;
        #pragma unroll
        for (int j = 0; j < 2; j++)
            cp_async16(adst + j * 16u, asrc + j * 4);
        const float* bsrc = wB + (size_t)(c * 32) * DIM;
        const uint32_t bdst = Bs(b) + (uint32_t)(brow * QB_STRIDE + bcol) * 4u;
        #pragma unroll
        for (int j = 0; j < 4; j++)
            cp_async16(bdst + j * 16u, bsrc + j * 4);
    };

    float acc[2][8][4];
    #pragma unroll
    for (int i = 0; i < 2; i++)
        #pragma unroll
        for (int j = 0; j < 8; j++)
            #pragma unroll
            for (int r = 0; r < 4; r++) acc[i][j][r] = 0.f;

    issue_chunk(0, 0); cp_commit();
    issue_chunk(1, 1); cp_commit();

    for (int c = 0; c < NCHUNK; c++) {
        const int b = c % QSTAGES;
        cp_wait<1>();
        __syncthreads();
        if (c + 2 < NCHUNK) issue_chunk(c + 2, (c + 2) % QSTAGES);
        cp_commit();

        const uint32_t* Ap = (const uint32_t*)(smem + (size_t)b * QBUF_FLOATS);
        const uint32_t* Bp = (const uint32_t*)(smem + (size_t)b * QBUF_FLOATS + QA_FLOATS);

        #pragma unroll
        for (int kk8 = 0; kk8 < 4; kk8++) {
            const int kk = kk8 * 8;
            uint32_t bb[8][2];
            #pragma unroll
            for (int j = 0; j < 8; j++) {
                const int n = wn * 64 + j * 8 + g;
                bb[j][0] = Bp[(kk + tg)     * QB_STRIDE + n];
                bb[j][1] = Bp[(kk + tg + 4) * QB_STRIDE + n];
            }
            #pragma unroll
            for (int i = 0; i < 2; i++) {
                const int r = wm * 32 + i * 16 + g;
                uint32_t ah[4];
                ah[0] = Ap[(r)     * QA_STRIDE + kk + tg];
                ah[1] = Ap[(r + 8) * QA_STRIDE + kk + tg];
                ah[2] = Ap[(r)     * QA_STRIDE + kk + tg + 4];
                ah[3] = Ap[(r + 8) * QA_STRIDE + kk + tg + 4];
                #pragma unroll
                for (int j = 0; j < 8; j++)
                    mma_tf32(acc[i][j], ah, bb[j]);
            }
        }
    }

    #pragma unroll
    for (int j = 0; j < 8; j++) {
        const int n = col0 + wn * 64 + j * 8 + 2 * tg;
        const float2 bb = *(const float2*)(bias + n);
        #pragma unroll
        for (int i = 0; i < 2; i++) {
            const int r = row0 + wm * 32 + i * 16 + g;
            float2 o0 = make_float2(acc[i][j][0] + bb.x, acc[i][j][1] + bb.y);
            float2 o1 = make_float2(acc[i][j][2] + bb.x, acc[i][j][3] + bb.y);
            *(float2*)(out + (size_t)r * DIM + n)       = o0;
            *(float2*)(out + (size_t)(r + 8) * DIM + n) = o1;
        }
    }
}

// ---------------------------------------------------------------------------
// Stage 2: per-head RMSNorm + RoPE applied in place to g_q and g_k.
// ---------------------------------------------------------------------------
__global__ __launch_bounds__(256) void rms_rope_kernel(
    const float* __restrict__ cosb, const float* __restrict__ sinb,
    const float* __restrict__ gq, const float* __restrict__ gk)
{
    const int gw   = (blockIdx.x * blockDim.x + threadIdx.x) >> 5;
    const int lane = threadIdx.x & 31;
    const int rows = S_LEN * HEADS;
    if (gw >= 2 * rows) return;

    const int t  = (gw >= rows) ? 1 : 0;
    const int rr = t ? (gw - rows) : gw;
    const int s  = rr / HEADS;

    float* ptr = (t ? g_k : g_q) + (size_t)rr * HEAD_DIM;
    const float* g = t ? gk : gq;

    float4 vx = *(float4*)(ptr + lane * 4);
    float ss = vx.x * vx.x + vx.y * vx.y + vx.z * vx.z + vx.w * vx.w;
    #pragma unroll
    for (int o = 16; o > 0; o >>= 1) ss += __shfl_xor_sync(0xffffffffu, ss, o);
    const float rnorm = rsqrtf(ss * (1.0f / HEAD_DIM) + 1e-6f);

    float4 gg = *(const float4*)(g + lane * 4);
    vx.x *= rnorm * gg.x; vx.y *= rnorm * gg.y;
    vx.z *= rnorm * gg.z; vx.w *= rnorm * gg.w;

    float4 c  = *(const float4*)(cosb + (size_t)s * HEAD_DIM + lane * 4);
    float4 sn = *(const float4*)(sinb + (size_t)s * HEAD_DIM + lane * 4);
    float4 o;
    o.x = vx.x * c.x - vx.y * sn.x;
    o.y = vx.y * c.y + vx.x * sn.y;
    o.z = vx.z * c.z - vx.w * sn.z;
    o.w = vx.w * c.w + vx.z * sn.w;
    *(float4*)(ptr + lane * 4) = o;
}

// ===========================================================================
// Stage 3: flash attention on mma.sync tf32.
// CTA: 128 q-rows x 1 head, 512 threads, 16 warps (wm 0-7, wh 0-1).
// KV tile 128 (16 iterations instead of 32 -> half the barriers/reductions).
// P (128x128, stride 132) ALIASES the K buffer: after the row-max
// __syncthreads all warps have finished S-MMAs, so K is dead.
// Layout (u32): Qh 128*132 | Ks/Ph 128*132 | Vs 128*136 | Rmax 256 | Rsum 256
// ===========================================================================
#define AT_THREADS 512
#define AT_KV 128
#define AT_QH 0
#define AT_KS (AT_QH + 128*132)
#define AT_VS (AT_KS + 128*132)
#define AT_RMAX (AT_VS + 128*136)
#define AT_RSUM (AT_RMAX + 256)
#define AT_TOTAL (AT_RSUM + 256)
#define AT_SMEM_BYTES (AT_TOTAL * 4)             // 206848

__global__ __launch_bounds__(AT_THREADS, 1) void attn_mma_kernel(float* __restrict__ out)
{
    extern __shared__ uint32_t smu[];
    uint32_t* Qh = smu + AT_QH;
    uint32_t* Ks = smu + AT_KS;      // aliased by Ph after S-phase
    uint32_t* Vs = smu + AT_VS;
    uint32_t* Ph = smu + AT_KS;      // alias
    float* Rmax = (float*)(smu + AT_RMAX);
    float* Rsum = (float*)(smu + AT_RSUM);

    const int h    = blockIdx.y;
    const int q0   = blockIdx.x * 128;
    const int tid  = threadIdx.x;
    const int wid  = tid >> 5;
    const int lane = tid & 31;
    const int g    = lane >> 2;
    const int tg   = lane & 3;
    const int wm   = wid >> 1;      // 0..7 -> q row-block (16 rows)
    const int wh   = wid & 1;       // kv/d column half (64 wide)
    const int ri0  = wm * 16 + g;   // 0..127
    const int ri1  = ri0 + 8;

    const float scale = 0.08838834764831845f;

    // ---- load Q tile (128 rows, scaled, tf32) ----
    for (int i = tid; i < 128 * 32; i += AT_THREADS) {
        const int r  = i >> 5;
        const int c4 = (i & 31) * 4;
        float4 v = *(const float4*)(g_q + ((size_t)(q0 + r) * HEADS + h) * HEAD_DIM + c4);
        uint4 hh;
        hh.x = tf32_rna(v.x * scale);
        hh.y = tf32_rna(v.y * scale);
        hh.z = tf32_rna(v.z * scale);
        hh.w = tf32_rna(v.w * scale);
        *(uint4*)(Qh + r * 132 + c4) = hh;
    }

    float m0 = -INFINITY, m1 = -INFINITY, l0 = 0.f, l1 = 0.f;
    float o[8][4];
    #pragma unroll
    for (int j = 0; j < 8; j++)
        #pragma unroll
        for (int r = 0; r < 4; r++) o[j][r] = 0.f;

    for (int kv0 = 0; kv0 < S_LEN; kv0 += AT_KV) {
        __syncthreads();   // previous tile's Ph/Vs fully consumed
        // ---- load K, V tiles (128 rows each, tf32) ----
        for (int i = tid; i < 128 * 32; i += AT_THREADS) {
            const int r  = i >> 5;
            const int c4 = (i & 31) * 4;
            float4 kv4 = *(const float4*)(g_k + ((size_t)(kv0 + r) * HEADS + h) * HEAD_DIM + c4);
            uint4 t;
            t.x = tf32_rna(kv4.x); t.y = tf32_rna(kv4.y);
            t.z = tf32_rna(kv4.z); t.w = tf32_rna(kv4.w);
            *(uint4*)(Ks + r * 132 + c4) = t;
            float4 vv4 = *(const float4*)(g_v + ((size_t)(kv0 + r) * HEADS + h) * HEAD_DIM + c4);
            uint4 u;
            u.x = tf32_rna(vv4.x); u.y = tf32_rna(vv4.y);
            u.z = tf32_rna(vv4.z); u.w = tf32_rna(vv4.w);
            *(uint4*)(Vs + r * 136 + c4) = u;
        }
        __syncthreads();

        // ---- S = Q K^T (warp: 16 q-rows x 64 kv-cols) ----
        float s[8][4];
        #pragma unroll
        for (int j = 0; j < 8; j++)
            #pragma unroll
            for (int r = 0; r < 4; r++) s[j][r] = 0.f;

        #pragma unroll
        for (int kk8 = 0; kk8 < 16; kk8++) {
            const int kk = kk8 * 8;
            uint32_t ah[4];
            ah[0] = Qh[ri0 * 132 + kk + tg];
            ah[1] = Qh[ri1 * 132 + kk + tg];
            ah[2] = Qh[ri0 * 132 + kk + tg + 4];
            ah[3] = Qh[ri1 * 132 + kk + tg + 4];
            #pragma unroll
            for (int j = 0; j < 8; j++) {
                const int nv = wh * 64 + j * 8 + g;
                uint32_t bb[2];
                bb[0] = Ks[nv * 132 + kk + tg];
                bb[1] = Ks[nv * 132 + kk + tg + 4];
                mma_tf32(s[j], ah, bb);
            }
        }

        // ---- row max over this warp's 64 cols, then cross-half ----
        float mx0 = -INFINITY, mx1 = -INFINITY;
        #pragma unroll
        for (int j = 0; j < 8; j++) {
            mx0 = fmaxf(mx0, fmaxf(s[j][0], s[j][1]));
            mx1 = fmaxf(mx1, fmaxf(s[j][2], s[j][3]));
        }
        mx0 = fmaxf(mx0, __shfl_xor_sync(0xffffffffu, mx0, 1));
        mx0 = fmaxf(mx0, __shfl_xor_sync(0xffffffffu, mx0, 2));
        mx1 = fmaxf(mx1, __shfl_xor_sync(0xffffffffu, mx1, 1));
        mx1 = fmaxf(mx1, __shfl_xor_sync(0xffffffffu, mx1, 2));
        if (tg == 0) {
            Rmax[wh * 128 + ri0] = mx0;
            Rmax[wh * 128 + ri1] = mx1;
        }
        __syncthreads();   // also: all warps done with Ks -> Ph may overwrite
        const float mn0 = fmaxf(m0, fmaxf(Rmax[ri0], Rmax[128 + ri0]));
        const float mn1 = fmaxf(m1, fmaxf(Rmax[ri1], Rmax[128 + ri1]));
        const float alpha0 = __expf(m0 - mn0);
        const float alpha1 = __expf(m1 - mn1);

        // ---- p = exp(s - m), stage tf32 P into Ks-aliased buffer ----
        float sum0 = 0.f, sum1 = 0.f;
        #pragma unroll
        for (int j = 0; j < 8; j++) {
            const int col = wh * 64 + j * 8 + 2 * tg;
            const float p0 = __expf(s[j][0] - mn0);
            const float p1 = __expf(s[j][1] - mn0);
            const float p2 = __expf(s[j][2] - mn1);
            const float p3 = __expf(s[j][3] - mn1);
            sum0 += p0 + p1;
            sum1 += p2 + p3;
            Ph[ri0 * 132 + col]     = tf32_rna(p0);
            Ph[ri0 * 132 + col + 1] = tf32_rna(p1);
            Ph[ri1 * 132 + col]     = tf32_rna(p2);
            Ph[ri1 * 132 + col + 1] = tf32_rna(p3);
        }
        sum0 += __shfl_xor_sync(0xffffffffu, sum0, 1);
        sum0 += __shfl_xor_sync(0xffffffffu, sum0, 2);
        sum1 += __shfl_xor_sync(0xffffffffu, sum1, 1);
        sum1 += __shfl_xor_sync(0xffffffffu, sum1, 2);
        if (tg == 0) {
            Rsum[wh * 128 + ri0] = sum0;
            Rsum[wh * 128 + ri1] = sum1;
        }
        __syncthreads();
        l0 = l0 * alpha0 + Rsum[ri0] + Rsum[128 + ri0];
        l1 = l1 * alpha1 + Rsum[ri1] + Rsum[128 + ri1];
        m0 = mn0; m1 = mn1;

        #pragma unroll
        for (int j = 0; j < 8; j++) {
            o[j][0] *= alpha0; o[j][1] *= alpha0;
            o[j][2] *= alpha1; o[j][3] *= alpha1;
        }

        // ---- O += P V (kv depth 128) ----
        #pragma unroll
        for (int kk8 = 0; kk8 < 16; kk8++) {
            const int kk = kk8 * 8;
            uint32_t ah[4];
            ah[0] = Ph[ri0 * 132 + kk + tg];
            ah[1] = Ph[ri1 * 132 + kk + tg];
            ah[2] = Ph[ri0 * 132 + kk + tg + 4];
            ah[3] = Ph[ri1 * 132 + kk + tg + 4];
            #pragma unroll
            for (int j = 0; j < 8; j++) {
                const int nd = wh * 64 + j * 8 + g;
                uint32_t bb[2];
                bb[0] = Vs[(kk + tg)     * 136 + nd];
                bb[1] = Vs[(kk + tg + 4) * 136 + nd];
                mma_tf32(o[j], ah, bb);
            }
        }
    }

    const float inv0 = 1.f / l0;
    const float inv1 = 1.f / l1;
    #pragma unroll
    for (int j = 0; j < 8; j++) {
        const int d = h * HEAD_DIM + wh * 64 + j * 8 + 2 * tg;
        *(float2*)(out + (size_t)(q0 + ri0) * DIM + d) =
            make_float2(o[j][0] * inv0, o[j][1] * inv0);
        *(float2*)(out + (size_t)(q0 + ri1) * DIM + d) =
            make_float2(o[j][2] * inv1, o[j][3] * inv1);
    }
}

// ---------------------------------------------------------------------------
extern "C" void kernel_launch(void* const* d_in, const int* in_sizes, int n_in,
                              void* d_out, int out_size)
{
    (void)in_sizes; (void)n_in; (void)out_size;
    const float* x  = (const float*)d_in[0];
    const float* cs = (const float*)d_in[1];
    const float* sn = (const float*)d_in[2];
    const float* Wq = (const float*)d_in[3];
    const float* bq = (const float*)d_in[4];
    const float* Wk = (const float*)d_in[5];
    const float* bk = (const float*)d_in[6];
    const float* Wv = (const float*)d_in[7];
    const float* bv = (const float*)d_in[8];
    const float* gq = (const float*)d_in[9];
    const float* gk = (const float*)d_in[10];
    float* out = (float*)d_out;

    // Stage 0: one-shot tf32 rounding of x and W
    tf32_prep_kernel<<<2048, 256>>>(x, Wq, Wk, Wv);

    // Stage 1: QKV projections (mma.sync tf32, pure LDS+MMA hot loop)
    cudaFuncSetAttribute(qkv_mma_kernel, cudaFuncAttributeMaxDynamicSharedMemorySize,
                         QSMEM_BYTES);
    dim3 gg(DIM / 256, S_LEN / 128, 3);
    qkv_mma_kernel<<<gg, QTHREADS, QSMEM_BYTES>>>(bq, bk, bv);

    // Stage 2: RMSNorm + RoPE on q, k
    const int warps  = 2 * S_LEN * HEADS;
    const int thr    = 256;
    const int blocks = (warps * 32 + thr - 1) / thr;
    rms_rope_kernel<<<blocks, thr>>>(cs, sn, gq, gk);

    // Stage 3: attention (mma.sync tf32, kv tile 128, P aliases K)
    cudaFuncSetAttribute(attn_mma_kernel, cudaFuncAttributeMaxDynamicSharedMemorySize,
                         AT_SMEM_BYTES);
    dim3 ga(S_LEN / 128, HEADS);
    attn_mma_kernel<<<ga, AT_THREADS, AT_SMEM_BYTES>>>(out);
}